// round 5
// baseline (speedup 1.0000x reference)
#include <cuda_runtime.h>
#include <math.h>

// B=8 S=512 FDIM=512 SUB=4 DIM=128 HEADS=8 DH=64 INNER=512
// T=2176 (2048+128 mem), NB=34, N_HASHES=4, BUCKET=64, C=136, 4T=8704

__device__ float g_x1 [8*2048*128];
__device__ float g_x2 [8*2048*128];
__device__ float g_ain[8*2048*128];
__device__ float g_aq [8*2176*128];    // packed qkv GEMM input
__device__ float g_am [8*2048*512];    // packed attention output (row-major)
__device__ float g_qk [8*8*2176*64];
__device__ float g_v  [8*8*2176*64];
__device__ float g_ao [8*8*2176*64];
__device__ int   g_bkt [48*8704];
__device__ int   g_st  [48*8704];
__device__ int   g_undo[48*8704];
__device__ float g_so  [48*8704*64];
__device__ float g_slog[48*8704];
__device__ float g_ff  [8*2048*512];

// ---- embed: features + positional encoding, init both streams ----
__global__ void __launch_bounds__(256) k_embed(const float* __restrict__ feat){
    int idx = blockIdx.x*256 + threadIdx.x;          // 8*2048*128
    int b = idx >> 18, r = idx & 262143;
    int t = r >> 7, d = r & 127;
    int s = t >> 2, f = ((t & 3) << 7) + d;
    float inv = expf(-(2.0f*(float)f/512.0f)*9.210340371976184f);
    float ang = (float)s * inv;
    float pe = (f & 1) ? cosf(ang) : sinf(ang);
    float v = feat[(b*512 + s)*512 + f] + pe;
    g_x1[idx] = v; g_x2[idx] = v;
}

// ---- layernorm over 128; pack!=0 remaps rows b*2048+t -> b*2176+t ----
__global__ void __launch_bounds__(128) k_layernorm(const float* __restrict__ in1,
                                                   const float* __restrict__ in2,
                                                   float* __restrict__ outp,
                                                   const float* __restrict__ gam,
                                                   const float* __restrict__ bet,
                                                   int pack){
    int row = blockIdx.x, d = threadIdx.x;
    float x = in1[row*128 + d];
    if (in2) x = 0.5f*(x + in2[row*128 + d]);
    __shared__ float sh[4];
    float s = x;
#pragma unroll
    for (int o=16;o>0;o>>=1) s += __shfl_xor_sync(0xffffffffu, s, o);
    if ((d & 31) == 0) sh[d>>5] = s;
    __syncthreads();
    float mean = (sh[0]+sh[1]+sh[2]+sh[3]) * (1.0f/128.0f);
    float c = x - mean;
    __syncthreads();
    float v = c*c;
#pragma unroll
    for (int o=16;o>0;o>>=1) v += __shfl_xor_sync(0xffffffffu, v, o);
    if ((d & 31) == 0) sh[d>>5] = v;
    __syncthreads();
    float var = (sh[0]+sh[1]+sh[2]+sh[3]) * (1.0f/128.0f);
    int orow = pack ? row + (row>>11)*128 : row;
    outp[orow*128 + d] = c * rsqrtf(var + 1e-5f) * gam[d] + bet[d];
}

// ---- fill mem rows of packed qkv input ----
__global__ void __launch_bounds__(256) k_memfill(const float* __restrict__ mem){
    int idx = blockIdx.x*256 + threadIdx.x;          // 8*128*128/4 float4
    int b = idx >> 12, r = idx & 4095;
    float4 v = ((const float4*)mem)[r];
    ((float4*)(g_aq + (b*2176 + 2048)*128))[r] = v;
}

// ---- repack attention output [bh][t][64] -> [b*2048+t][512] ----
__global__ void __launch_bounds__(256) k_merge(){
    int idx = blockIdx.x*256 + threadIdx.x;          // 8*2048*128 float4 (2,097,152)
    int m = idx >> 7, c4 = idx & 127;
    int head = c4 >> 4, d4 = c4 & 15;
    int b = m >> 11, t = m & 2047;
    float4 v = ((const float4*)(g_ao + (((b<<3)+head)*2176 + t)*64))[d4];
    ((float4*)(g_am + m*512))[c4] = v;
}

// ---- GEMM: plain A [M][K], 64x128 tiles, 4x8 micro-tile ----
struct EQKV {
    float* out;
    __device__ __forceinline__ void operator()(int m, int n, float v) const {
        int b = m / 2176, t = m - b*2176;
        out[(((b<<3) + (n>>6))*2176 + t)*64 + (n & 63)] = v;
    }
};
struct EAddBias {
    float* out; const float* bias; int ld;
    __device__ __forceinline__ void operator()(int m, int n, float v) const {
        out[m*ld + n] += v + bias[n];
    }
};
struct EGelu {
    float* out; const float* bias;
    __device__ __forceinline__ void operator()(int m, int n, float v) const {
        float h = v + bias[n];
        out[m*512 + n] = 0.5f*h*(1.0f + erff(h*0.7071067811865475f));
    }
};

template<class EP>
__global__ void __launch_bounds__(256) k_gemm(const float* __restrict__ A, int K,
                                              const float* __restrict__ Bm, int N,
                                              EP ep){
    __shared__ float As[16][68];    // [k][m]
    __shared__ float Bs[16][132];   // [k][n]
    int bm = blockIdx.y*64, bn = blockIdx.x*128;
    int tid = threadIdx.x, tx = tid & 15, ty = tid >> 4;
    int arow = tid >> 2, akq = tid & 3;              // A fill: 256 float4
    float acc[4][8] = {};
    for (int k0 = 0; k0 < K; k0 += 16){
        float4 av = *(const float4*)(A + (bm+arow)*K + k0 + akq*4);
        As[akq*4+0][arow] = av.x;
        As[akq*4+1][arow] = av.y;
        As[akq*4+2][arow] = av.z;
        As[akq*4+3][arow] = av.w;
#pragma unroll
        for (int u=0;u<2;u++){
            int i = tid + 256*u;                     // 512 float4 = 128*16
            int v4 = i & 31, kk = i >> 5;
            *(float4*)&Bs[kk][v4*4] = *(const float4*)(Bm + (k0+kk)*N + bn + v4*4);
        }
        __syncthreads();
#pragma unroll
        for (int kk=0;kk<16;kk++){
            float4 a4 = *(float4*)&As[kk][ty*4];
            float4 b0 = *(float4*)&Bs[kk][tx*8];
            float4 b1 = *(float4*)&Bs[kk][tx*8+4];
            float avv[4] = {a4.x,a4.y,a4.z,a4.w};
            float bvv[8] = {b0.x,b0.y,b0.z,b0.w,b1.x,b1.y,b1.z,b1.w};
#pragma unroll
            for (int i=0;i<4;i++)
#pragma unroll
                for (int j=0;j<8;j++) acc[i][j] = fmaf(avv[i], bvv[j], acc[i][j]);
        }
        __syncthreads();
    }
#pragma unroll
    for (int i=0;i<4;i++)
#pragma unroll
        for (int j=0;j<8;j++) ep(bm + ty*4 + i, bn + tx*8 + j, acc[i][j]);
}

// ---- LSH bucket assignment ----
__global__ void __launch_bounds__(128) k_buckets(const float* __restrict__ rot){
    __shared__ float srot[4352];                     // [f=64][h*17+i]
    int tid = threadIdx.x;
    for (int i = tid; i < 4352; i += 128) srot[i] = rot[i];
    __syncthreads();
    int bh = blockIdx.x, t = blockIdx.y*128 + tid;
    int b = bh / 6, head = 2 + bh % 6;
    const float* qp = g_qk + (((b<<3) + head)*2176 + t)*64;
    float rv[68];
#pragma unroll
    for (int u=0;u<68;u++) rv[u] = 0.0f;
    for (int f=0; f<64; f++){
        float qf = qp[f];
        const float* rp = &srot[f*68];
#pragma unroll
        for (int u=0;u<68;u++) rv[u] = fmaf(qf, rp[u], rv[u]);
    }
#pragma unroll
    for (int h=0; h<4; h++){
        float best = rv[h*17]; int bi = 0;
#pragma unroll
        for (int i=1;i<17;i++){ float v = rv[h*17+i]; if (v > best){ best = v; bi = i; } }
#pragma unroll
        for (int i=0;i<17;i++){ float v = -rv[h*17+i]; if (v > best){ best = v; bi = 17+i; } }
        g_bkt[bh*8704 + h*2176 + t] = bi + h*34;
    }
}

// ---- stable counting sort over 136 bins ----
__global__ void __launch_bounds__(64) k_sort(){
    __shared__ int hist[64][136];
    __shared__ int base[136];
    int bh = blockIdx.x, t = threadIdx.x;
    int* hrow = hist[t];
    for (int i=0;i<136;i++) hrow[i] = 0;
    const int* bk = g_bkt + bh*8704;
    int i0 = t*136;
    for (int i=0;i<136;i++) hrow[bk[i0+i]]++;
    __syncthreads();
    for (int c = t; c < 136; c += 64){
        int run = 0;
        for (int tt=0; tt<64; tt++){ int v = hist[tt][c]; hist[tt][c] = run; run += v; }
        base[c] = run;
    }
    __syncthreads();
    if (t == 0){
        int run = 0;
        for (int c=0;c<136;c++){ int v = base[c]; base[c] = run; run += v; }
    }
    __syncthreads();
    for (int i=0;i<136;i++){
        int idx = i0 + i, bb = bk[idx];
        int pos = base[bb] + hrow[bb]; hrow[bb]++;
        g_st  [bh*8704 + pos] = idx % 2176;
        g_undo[bh*8704 + idx] = pos;
    }
}

// ---- LSH chunk attention: gather-on-the-fly, 64 q x 128 kv ----
__global__ void __launch_bounds__(256) k_lsh_attn(){
    extern __shared__ float sm[];
    float* sqk   = sm;                  // 128*68
    float* sv    = sm + 8704;           // 128*68
    float* sd    = sm + 17408;          // 64*128
    float* scale = sm + 25600;          // 128
    int*   skt   = (int*)(sm + 25728);  // 128
    int bh = blockIdx.x, c = blockIdx.y, tid = threadIdx.x;
    int base  = bh*8704 + c*64;
    int pbase = bh*8704 + ((c + 135) % 136)*64;
    int b = bh / 6, head = 2 + bh % 6;
    int bhh = (b<<3) + head;
    for (int p = tid; p < 128*16; p += 256){
        int row = p >> 4, v4 = p & 15;
        int src = (row < 64) ? g_st[base + row] : g_st[pbase + row - 64];
        *(float4*)&sqk[row*68 + v4*4] = ((const float4*)(g_qk + (bhh*2176 + src)*64))[v4];
        *(float4*)&sv [row*68 + v4*4] = ((const float4*)(g_v  + (bhh*2176 + src)*64))[v4];
    }
    if (tid < 128)
        skt[tid] = (tid < 64) ? g_st[base + tid] : g_st[pbase + tid - 64];
    __syncthreads();
    if (tid < 128){
        float s = 0.f;
#pragma unroll
        for (int d=0; d<64; d+=4){
            float4 v = *(float4*)&sqk[tid*68 + d];
            s += v.x*v.x + v.y*v.y + v.z*v.z + v.w*v.w;
        }
        scale[tid] = 1.0f / fmaxf(sqrtf(s), 1e-12f);
    }
    __syncthreads();
    int ty = tid >> 4, tx = tid & 15;
    int i0 = ty*4, j0 = tx*8;
    {
        float acc[4][8] = {};
        for (int d=0; d<64; d+=4){
            float4 a[4], bb[8];
#pragma unroll
            for (int i=0;i<4;i++) a[i]  = *(float4*)&sqk[(i0+i)*68 + d];
#pragma unroll
            for (int j=0;j<8;j++) bb[j] = *(float4*)&sqk[(j0+j)*68 + d];
#pragma unroll
            for (int i=0;i<4;i++)
#pragma unroll
                for (int j=0;j<8;j++){
                    acc[i][j] = fmaf(a[i].x, bb[j].x, acc[i][j]);
                    acc[i][j] = fmaf(a[i].y, bb[j].y, acc[i][j]);
                    acc[i][j] = fmaf(a[i].z, bb[j].z, acc[i][j]);
                    acc[i][j] = fmaf(a[i].w, bb[j].w, acc[i][j]);
                }
        }
#pragma unroll
        for (int i=0;i<4;i++){
            int tq = skt[i0+i];
#pragma unroll
            for (int j=0;j<8;j++){
                int tk = skt[j0+j];
                float v = acc[i][j]*scale[j0+j]*0.125f;
                if (tq < tk)       v = -1e9f;
                else if (tq == tk) v = -5e4f;
                sd[(i0+i)*128 + j0 + j] = v;
            }
        }
    }
    __syncthreads();
    {   // softmax + logsumexp per row
        int warp = tid >> 5, lane = tid & 31;
        for (int rr=0; rr<8; rr++){
            int row = warp*8 + rr;
            float d0[4];
#pragma unroll
            for (int j=0;j<4;j++) d0[j] = sd[row*128 + lane + 32*j];
            float m = fmaxf(fmaxf(d0[0],d0[1]), fmaxf(d0[2],d0[3]));
#pragma unroll
            for (int o=16;o>0;o>>=1) m = fmaxf(m, __shfl_xor_sync(0xffffffffu, m, o));
            float p[4], s = 0.f;
#pragma unroll
            for (int j=0;j<4;j++){ p[j] = expf(d0[j]-m); s += p[j]; }
#pragma unroll
            for (int o=16;o>0;o>>=1) s += __shfl_xor_sync(0xffffffffu, s, o);
            float inv = 1.0f/s;
#pragma unroll
            for (int j=0;j<4;j++) sd[row*128 + lane + 32*j] = p[j]*inv;
            if (lane == 0) g_slog[base + row] = m + logf(s);
        }
    }
    __syncthreads();
    {
        int d0 = tx*4;
        float acc[4][4] = {};
        for (int j=0; j<128; j+=4){
            float4 p[4], vv[4];
#pragma unroll
            for (int i=0;i<4;i++)    p[i]  = *(float4*)&sd[(i0+i)*128 + j];
#pragma unroll
            for (int j2=0;j2<4;j2++) vv[j2] = *(float4*)&sv[(j+j2)*68 + d0];
#pragma unroll
            for (int i=0;i<4;i++){
                acc[i][0] = fmaf(p[i].x, vv[0].x, acc[i][0]);
                acc[i][0] = fmaf(p[i].y, vv[1].x, acc[i][0]);
                acc[i][0] = fmaf(p[i].z, vv[2].x, acc[i][0]);
                acc[i][0] = fmaf(p[i].w, vv[3].x, acc[i][0]);
                acc[i][1] = fmaf(p[i].x, vv[0].y, acc[i][1]);
                acc[i][1] = fmaf(p[i].y, vv[1].y, acc[i][1]);
                acc[i][1] = fmaf(p[i].z, vv[2].y, acc[i][1]);
                acc[i][1] = fmaf(p[i].w, vv[3].y, acc[i][1]);
                acc[i][2] = fmaf(p[i].x, vv[0].z, acc[i][2]);
                acc[i][2] = fmaf(p[i].y, vv[1].z, acc[i][2]);
                acc[i][2] = fmaf(p[i].z, vv[2].z, acc[i][2]);
                acc[i][2] = fmaf(p[i].w, vv[3].z, acc[i][2]);
                acc[i][3] = fmaf(p[i].x, vv[0].w, acc[i][3]);
                acc[i][3] = fmaf(p[i].y, vv[1].w, acc[i][3]);
                acc[i][3] = fmaf(p[i].z, vv[2].w, acc[i][3]);
                acc[i][3] = fmaf(p[i].w, vv[3].w, acc[i][3]);
            }
        }
#pragma unroll
        for (int i=0;i<4;i++)
#pragma unroll
            for (int d=0;d<4;d++) g_so[(base + i0 + i)*64 + d0 + d] = acc[i][d];
    }
}

// ---- unsort + multi-hash logsumexp combine ----
__global__ void __launch_bounds__(64) k_unsort(){
    int t = blockIdx.x, bh = blockIdx.y, d = threadIdx.x;
    __shared__ int pos[4]; __shared__ float w[4];
    if (d < 4){
        int p = g_undo[bh*8704 + d*2176 + t];
        pos[d] = p; w[d] = g_slog[bh*8704 + p];
    }
    __syncthreads();
    if (d == 0){
        float m = fmaxf(fmaxf(w[0],w[1]), fmaxf(w[2],w[3]));
        float s = 0.f;
        for (int h=0;h<4;h++){ w[h] = expf(w[h]-m); s += w[h]; }
        float inv = 1.0f/s;
        for (int h=0;h<4;h++) w[h] *= inv;
    }
    __syncthreads();
    float o = 0.f;
    for (int h=0;h<4;h++) o += w[h]*g_so[(bh*8704 + pos[h])*64 + d];
    int b = bh / 6, head = 2 + bh % 6;
    g_ao[(((b<<3) + head)*2176 + t)*64 + d] = o;
}

// ---- local windowed attention: 64 q x 256 kv, 512 threads ----
__global__ void __launch_bounds__(512) k_local_attn(){
    extern __shared__ float sm[];
    float* skv   = sm;            // 256*68 (0-127 prev win, 128-255 own)
    float* sv    = sm + 17408;    // 256*68
    float* sd    = sm + 34816;    // 64*256
    float* scale = sm + 51200;    // 256
    int bh = blockIdx.x, b = bh >> 1, head = bh & 1;
    int win = blockIdx.y, half = blockIdx.z;
    int tid = threadIdx.x;
    const float* qbase = g_qk + (((b<<3) + head)*2176)*64;
    const float* vbase = g_v  + (((b<<3) + head)*2176)*64;
    int q0 = win*128 + half*64;
    int qrow = 128 + half*64;
    for (int p = tid; p < 256*16; p += 512){
        int row = p >> 4, v4 = p & 15;
        float4 kv, vv;
        if (row < 128 && win == 0){
            kv = make_float4(0,0,0,0); vv = kv;
        } else {
            int t = (row < 128) ? (win-1)*128 + row : win*128 + row - 128;
            kv = ((const float4*)(qbase + t*64))[v4];
            vv = ((const float4*)(vbase + t*64))[v4];
        }
        *(float4*)&skv[row*68 + v4*4] = kv;
        *(float4*)&sv [row*68 + v4*4] = vv;
    }
    __syncthreads();
    if (tid < 256){
        float s = 0.f;
#pragma unroll
        for (int d=0;d<64;d+=4){
            float4 v = *(float4*)&skv[tid*68 + d];
            s += v.x*v.x + v.y*v.y + v.z*v.z + v.w*v.w;
        }
        scale[tid] = 1.0f / fmaxf(sqrtf(s), 1e-12f);
    }
    __syncthreads();
    int ty = tid >> 4, tx = tid & 15;     // ty 0..31 (2 rows), tx 0..15
    int i0 = ty*2;
    for (int jt=0; jt<2; jt++){
        int jb = tx*8 + jt*128;
        float acc[2][8] = {};
        for (int d=0; d<64; d+=4){
            float4 a[2], bb[8];
#pragma unroll
            for (int i=0;i<2;i++) a[i]  = *(float4*)&skv[(qrow+i0+i)*68 + d];
#pragma unroll
            for (int j=0;j<8;j++) bb[j] = *(float4*)&skv[(jb+j)*68 + d];
#pragma unroll
            for (int i=0;i<2;i++)
#pragma unroll
                for (int j=0;j<8;j++){
                    acc[i][j] = fmaf(a[i].x, bb[j].x, acc[i][j]);
                    acc[i][j] = fmaf(a[i].y, bb[j].y, acc[i][j]);
                    acc[i][j] = fmaf(a[i].z, bb[j].z, acc[i][j]);
                    acc[i][j] = fmaf(a[i].w, bb[j].w, acc[i][j]);
                }
        }
#pragma unroll
        for (int i=0;i<2;i++){
            int tq = q0 + i0 + i;
#pragma unroll
            for (int j=0;j<8;j++){
                int jc = jb + j;
                float v = acc[i][j]*scale[jc]*0.125f;
                if (jc < 128){
                    if (win == 0) v = -1e9f;
                    else {
                        int tk = (win-1)*128 + jc;
                        if (tq == tk) v = -5e4f; else if (tq < tk) v = -1e9f;
                    }
                } else {
                    int tk = win*128 + jc - 128;
                    if (tq == tk) v = -5e4f; else if (tq < tk) v = -1e9f;
                }
                sd[(i0+i)*256 + jc] = v;
            }
        }
    }
    __syncthreads();
    {   // softmax: 16 warps x 4 rows
        int warp = tid >> 5, lane = tid & 31;
        for (int rr=0; rr<4; rr++){
            int row = warp*4 + rr;
            float d0[8];
#pragma unroll
            for (int j=0;j<8;j++) d0[j] = sd[row*256 + lane + 32*j];
            float m = d0[0];
#pragma unroll
            for (int j=1;j<8;j++) m = fmaxf(m, d0[j]);
#pragma unroll
            for (int o=16;o>0;o>>=1) m = fmaxf(m, __shfl_xor_sync(0xffffffffu, m, o));
            float p[8], s = 0.f;
#pragma unroll
            for (int j=0;j<8;j++){ p[j] = expf(d0[j]-m); s += p[j]; }
#pragma unroll
            for (int o=16;o>0;o>>=1) s += __shfl_xor_sync(0xffffffffu, s, o);
            float inv = 1.0f/s;
#pragma unroll
            for (int j=0;j<8;j++) sd[row*256 + lane + 32*j] = p[j]*inv;
        }
    }
    __syncthreads();
    {
        int d0 = tx*4;
        float acc[2][4] = {};
        for (int j=0; j<256; j+=4){
            float4 p[2], vv[4];
#pragma unroll
            for (int i=0;i<2;i++)    p[i]  = *(float4*)&sd[(i0+i)*256 + j];
#pragma unroll
            for (int j2=0;j2<4;j2++) vv[j2] = *(float4*)&sv[(j+j2)*68 + d0];
#pragma unroll
            for (int i=0;i<2;i++){
                acc[i][0] = fmaf(p[i].x, vv[0].x, acc[i][0]);
                acc[i][0] = fmaf(p[i].y, vv[1].x, acc[i][0]);
                acc[i][0] = fmaf(p[i].z, vv[2].x, acc[i][0]);
                acc[i][0] = fmaf(p[i].w, vv[3].x, acc[i][0]);
                acc[i][1] = fmaf(p[i].x, vv[0].y, acc[i][1]);
                acc[i][1] = fmaf(p[i].y, vv[1].y, acc[i][1]);
                acc[i][1] = fmaf(p[i].z, vv[2].y, acc[i][1]);
                acc[i][1] = fmaf(p[i].w, vv[3].y, acc[i][1]);
                acc[i][2] = fmaf(p[i].x, vv[0].z, acc[i][2]);
                acc[i][2] = fmaf(p[i].y, vv[1].z, acc[i][2]);
                acc[i][2] = fmaf(p[i].z, vv[2].z, acc[i][2]);
                acc[i][2] = fmaf(p[i].w, vv[3].z, acc[i][2]);
                acc[i][3] = fmaf(p[i].x, vv[0].w, acc[i][3]);
                acc[i][3] = fmaf(p[i].y, vv[1].w, acc[i][3]);
                acc[i][3] = fmaf(p[i].z, vv[2].w, acc[i][3]);
                acc[i][3] = fmaf(p[i].w, vv[3].w, acc[i][3]);
            }
        }
#pragma unroll
        for (int i=0;i<2;i++)
#pragma unroll
            for (int d=0;d<4;d++)
                g_ao[(((b<<3) + head)*2176 + q0 + i0 + i)*64 + d0 + d] = acc[i][d];
    }
}

// ---- mean-pool over sequence ----
__global__ void __launch_bounds__(128) k_pool(const float* __restrict__ in, float* __restrict__ out){
    int b = blockIdx.x >> 2, sub = blockIdx.x & 3, d = threadIdx.x;
    const float* p = in + (b*2048 + sub)*128 + d;
    float s = 0.f;
    for (int i=0;i<512;i++) s += p[i*512];
    out[b*512 + sub*128 + d] = s * (1.0f/512.0f);
}

extern "C" void kernel_launch(void* const* d_in, const int* in_sizes, int n_in,
                              void* d_out, int out_size){
    const float* features  = (const float*)d_in[0];
    const float* w_qk      = (const float*)d_in[1];
    const float* w_v       = (const float*)d_in[2];
    const float* mem_kv    = (const float*)d_in[3];
    const float* w_out     = (const float*)d_in[4];
    const float* b_out     = (const float*)d_in[5];
    const float* ln1_g     = (const float*)d_in[6];
    const float* ln1_b     = (const float*)d_in[7];
    const float* ff_w1     = (const float*)d_in[8];
    const float* ff_b1     = (const float*)d_in[9];
    const float* ff_w2     = (const float*)d_in[10];
    const float* ff_b2     = (const float*)d_in[11];
    const float* ln2_g     = (const float*)d_in[12];
    const float* ln2_b     = (const float*)d_in[13];
    const float* lnf_g     = (const float*)d_in[14];
    const float* lnf_b     = (const float*)d_in[15];
    const float* rotations = (const float*)d_in[16];
    float* out = (float*)d_out;

    float *x1,*x2,*ain,*aq,*am,*qk,*vv,*ff;
    cudaGetSymbolAddress((void**)&x1,  g_x1);
    cudaGetSymbolAddress((void**)&x2,  g_x2);
    cudaGetSymbolAddress((void**)&ain, g_ain);
    cudaGetSymbolAddress((void**)&aq,  g_aq);
    cudaGetSymbolAddress((void**)&am,  g_am);
    cudaGetSymbolAddress((void**)&qk,  g_qk);
    cudaGetSymbolAddress((void**)&vv,  g_v);
    cudaGetSymbolAddress((void**)&ff,  g_ff);

    const int LSH_SMEM = 103424;
    const int LOC_SMEM = 205824;
    cudaFuncSetAttribute(k_lsh_attn,   cudaFuncAttributeMaxDynamicSharedMemorySize, LSH_SMEM);
    cudaFuncSetAttribute(k_local_attn, cudaFuncAttributeMaxDynamicSharedMemorySize, LOC_SMEM);

    k_embed<<<8192, 256>>>(features);

    for (int i = 0; i < 2; i++){
        k_layernorm<<<16384,128>>>(x2, (const float*)0, aq, ln1_g + i*128, ln1_b + i*128, 1);
        k_memfill<<<128,256>>>(mem_kv + i*128*128);
        EQKV eq; eq.out = qk;
        EQKV ev; ev.out = vv;
        k_gemm<<<dim3(4,272),256>>>(aq, 128, w_qk + i*128*512, 512, eq);
        k_gemm<<<dim3(4,272),256>>>(aq, 128, w_v  + i*128*512, 512, ev);
        k_local_attn<<<dim3(16,17,2),512,LOC_SMEM>>>();
        k_buckets<<<dim3(48,17),128>>>(rotations + i*64*4*17);
        k_sort<<<48,64>>>();
        k_lsh_attn<<<dim3(48,136),256,LSH_SMEM>>>();
        k_unsort<<<dim3(2176,48),64>>>();
        k_merge<<<8192,256>>>();
        EAddBias e1; e1.out = x1; e1.bias = b_out + i*128; e1.ld = 128;
        k_gemm<<<dim3(1,256),256>>>(am, 512, w_out + i*512*128, 128, e1);
        k_layernorm<<<16384,128>>>(x1, (const float*)0, ain, ln2_g + i*128, ln2_b + i*128, 0);
        EGelu eg; eg.out = ff; eg.bias = ff_b1 + i*512;
        k_gemm<<<dim3(4,256),256>>>(ain, 128, ff_w1 + i*128*512, 512, eg);
        EAddBias e2; e2.out = x2; e2.bias = ff_b2 + i*128; e2.ld = 128;
        k_gemm<<<dim3(1,256),256>>>(ff, 512, ff_w2 + i*512*128, 128, e2);
    }
    k_layernorm<<<16384,128>>>(x1, x2, ain, lnf_g, lnf_b, 0);
    k_pool<<<32,128>>>(ain, out);
}

// round 6
// speedup vs baseline: 1.0888x; 1.0888x over previous
#include <cuda_runtime.h>
#include <math.h>

// B=8 S=512 FDIM=512 SUB=4 DIM=128 HEADS=8 DH=64 INNER=512
// T=2176 (2048+128 mem), NB=34, N_HASHES=4, BUCKET=64, C=136, 4T=8704

__device__ float g_x1 [8*2048*128];
__device__ float g_x2 [8*2048*128];
__device__ float g_ain[8*2048*128];
__device__ float g_aq [8*2176*128];    // packed qkv GEMM input
__device__ float g_am [8*2048*512];    // merged attention output (row-major)
__device__ float g_qk [8*8*2176*64];
__device__ float g_v  [8*8*2176*64];
__device__ int   g_bkt [48*8704];
__device__ int   g_st  [48*8704];
__device__ int   g_undo[48*8704];
__device__ float g_so  [48*8704*64];
__device__ float g_slog[48*8704];
__device__ float g_ff  [8*2048*512];

// ---- embed: features + positional encoding, init both streams ----
__global__ void __launch_bounds__(256) k_embed(const float* __restrict__ feat){
    int idx = blockIdx.x*256 + threadIdx.x;          // 8*2048*128
    int b = idx >> 18, r = idx & 262143;
    int t = r >> 7, d = r & 127;
    int s = t >> 2, f = ((t & 3) << 7) + d;
    float inv = expf(-(2.0f*(float)f/512.0f)*9.210340371976184f);
    float ang = (float)s * inv;
    float pe = (f & 1) ? cosf(ang) : sinf(ang);
    float v = feat[(b*512 + s)*512 + f] + pe;
    g_x1[idx] = v; g_x2[idx] = v;
}

// ---- layernorm over 128; pack!=0 remaps rows b*2048+t -> b*2176+t ----
__global__ void __launch_bounds__(128) k_layernorm(const float* __restrict__ in1,
                                                   const float* __restrict__ in2,
                                                   float* __restrict__ outp,
                                                   const float* __restrict__ gam,
                                                   const float* __restrict__ bet,
                                                   int pack){
    int row = blockIdx.x, d = threadIdx.x;
    float x = in1[row*128 + d];
    if (in2) x = 0.5f*(x + in2[row*128 + d]);
    __shared__ float sh[4];
    float s = x;
#pragma unroll
    for (int o=16;o>0;o>>=1) s += __shfl_xor_sync(0xffffffffu, s, o);
    if ((d & 31) == 0) sh[d>>5] = s;
    __syncthreads();
    float mean = (sh[0]+sh[1]+sh[2]+sh[3]) * (1.0f/128.0f);
    float c = x - mean;
    __syncthreads();
    float v = c*c;
#pragma unroll
    for (int o=16;o>0;o>>=1) v += __shfl_xor_sync(0xffffffffu, v, o);
    if ((d & 31) == 0) sh[d>>5] = v;
    __syncthreads();
    float var = (sh[0]+sh[1]+sh[2]+sh[3]) * (1.0f/128.0f);
    int orow = pack ? row + (row>>11)*128 : row;
    outp[orow*128 + d] = c * rsqrtf(var + 1e-5f) * gam[d] + bet[d];
}

// ---- fill mem rows of packed qkv input ----
__global__ void __launch_bounds__(256) k_memfill(const float* __restrict__ mem){
    int idx = blockIdx.x*256 + threadIdx.x;          // 8*128*128/4 float4
    int b = idx >> 12, r = idx & 4095;
    float4 v = ((const float4*)mem)[r];
    ((float4*)(g_aq + (b*2176 + 2048)*128))[r] = v;
}

// ---- GEMM: plain A [M][K], 64x128 tiles, 4x8 micro-tile, double-buffered ----
struct EQKV {
    float* out;
    __device__ __forceinline__ void operator()(int m, int n, float v) const {
        int b = m / 2176, t = m - b*2176;
        out[(((b<<3) + (n>>6))*2176 + t)*64 + (n & 63)] = v;
    }
};
struct EAddBias {
    float* out; const float* bias; int ld;
    __device__ __forceinline__ void operator()(int m, int n, float v) const {
        out[m*ld + n] += v + bias[n];
    }
};
struct EGelu {
    float* out; const float* bias;
    __device__ __forceinline__ void operator()(int m, int n, float v) const {
        float h = v + bias[n];
        out[m*512 + n] = 0.5f*h*(1.0f + erff(h*0.7071067811865475f));
    }
};

template<class EP>
__global__ void __launch_bounds__(256) k_gemm(const float* __restrict__ A, int K,
                                              const float* __restrict__ Bm, int N,
                                              EP ep){
    __shared__ float As[2][16][68];    // [buf][k][m]
    __shared__ float Bs[2][16][132];   // [buf][k][n]
    int bm = blockIdx.y*64, bn = blockIdx.x*128;
    int tid = threadIdx.x, tx = tid & 15, ty = tid >> 4;
    int arow = tid >> 2, akq = tid & 3;       // A fill: 256 float4
    int bk = tid >> 5, bv4 = (tid & 31)*4;    // B fill: rows bk, bk+8
    float acc[4][8] = {};
    // prologue: tile 0 -> buf 0
    {
        float4 av  = *(const float4*)(A + (bm+arow)*K + akq*4);
        float4 bv0 = *(const float4*)(Bm + bk*N + bn + bv4);
        float4 bv1 = *(const float4*)(Bm + (bk+8)*N + bn + bv4);
        As[0][akq*4+0][arow] = av.x;
        As[0][akq*4+1][arow] = av.y;
        As[0][akq*4+2][arow] = av.z;
        As[0][akq*4+3][arow] = av.w;
        *(float4*)&Bs[0][bk][bv4]   = bv0;
        *(float4*)&Bs[0][bk+8][bv4] = bv1;
    }
    __syncthreads();
    int nt = K >> 4;
    for (int t = 0; t < nt; t++){
        int cur = t & 1, nxt = cur ^ 1;
        float4 nav, nbv0, nbv1;
        if (t+1 < nt){
            int k0 = (t+1) << 4;
            nav  = *(const float4*)(A + (bm+arow)*K + k0 + akq*4);
            nbv0 = *(const float4*)(Bm + (k0+bk)*N + bn + bv4);
            nbv1 = *(const float4*)(Bm + (k0+bk+8)*N + bn + bv4);
        }
#pragma unroll
        for (int kk=0;kk<16;kk++){
            float4 a4 = *(float4*)&As[cur][kk][ty*4];
            float4 b0 = *(float4*)&Bs[cur][kk][tx*8];
            float4 b1 = *(float4*)&Bs[cur][kk][tx*8+4];
            float avv[4] = {a4.x,a4.y,a4.z,a4.w};
            float bvv[8] = {b0.x,b0.y,b0.z,b0.w,b1.x,b1.y,b1.z,b1.w};
#pragma unroll
            for (int i=0;i<4;i++)
#pragma unroll
                for (int j=0;j<8;j++) acc[i][j] = fmaf(avv[i], bvv[j], acc[i][j]);
        }
        if (t+1 < nt){
            As[nxt][akq*4+0][arow] = nav.x;
            As[nxt][akq*4+1][arow] = nav.y;
            As[nxt][akq*4+2][arow] = nav.z;
            As[nxt][akq*4+3][arow] = nav.w;
            *(float4*)&Bs[nxt][bk][bv4]   = nbv0;
            *(float4*)&Bs[nxt][bk+8][bv4] = nbv1;
            __syncthreads();
        }
    }
#pragma unroll
    for (int i=0;i<4;i++)
#pragma unroll
        for (int j=0;j<8;j++) ep(bm + ty*4 + i, bn + tx*8 + j, acc[i][j]);
}

// ---- LSH bucket assignment ----
__global__ void __launch_bounds__(128) k_buckets(const float* __restrict__ rot){
    __shared__ float srot[4352];                     // [f=64][h*17+i]
    int tid = threadIdx.x;
    for (int i = tid; i < 4352; i += 128) srot[i] = rot[i];
    __syncthreads();
    int bh = blockIdx.x, t = blockIdx.y*128 + tid;
    int b = bh / 6, head = 2 + bh % 6;
    const float* qp = g_qk + (((b<<3) + head)*2176 + t)*64;
    float rv[68];
#pragma unroll
    for (int u=0;u<68;u++) rv[u] = 0.0f;
    for (int f=0; f<64; f++){
        float qf = qp[f];
        const float* rp = &srot[f*68];
#pragma unroll
        for (int u=0;u<68;u++) rv[u] = fmaf(qf, rp[u], rv[u]);
    }
#pragma unroll
    for (int h=0; h<4; h++){
        float best = rv[h*17]; int bi = 0;
#pragma unroll
        for (int i=1;i<17;i++){ float v = rv[h*17+i]; if (v > best){ best = v; bi = i; } }
#pragma unroll
        for (int i=0;i<17;i++){ float v = -rv[h*17+i]; if (v > best){ best = v; bi = 17+i; } }
        g_bkt[bh*8704 + h*2176 + t] = bi + h*34;
    }
}

// ---- stable counting sort over 136 bins ----
__global__ void __launch_bounds__(64) k_sort(){
    __shared__ int hist[64][136];
    __shared__ int base[136];
    int bh = blockIdx.x, t = threadIdx.x;
    int* hrow = hist[t];
    for (int i=0;i<136;i++) hrow[i] = 0;
    const int* bk = g_bkt + bh*8704;
    int i0 = t*136;
    for (int i=0;i<136;i++) hrow[bk[i0+i]]++;
    __syncthreads();
    for (int c = t; c < 136; c += 64){
        int run = 0;
        for (int tt=0; tt<64; tt++){ int v = hist[tt][c]; hist[tt][c] = run; run += v; }
        base[c] = run;
    }
    __syncthreads();
    if (t == 0){
        int run = 0;
        for (int c=0;c<136;c++){ int v = base[c]; base[c] = run; run += v; }
    }
    __syncthreads();
    for (int i=0;i<136;i++){
        int idx = i0 + i, bb = bk[idx];
        int pos = base[bb] + hrow[bb]; hrow[bb]++;
        g_st  [bh*8704 + pos] = idx % 2176;
        g_undo[bh*8704 + idx] = pos;
    }
}

// ---- LSH chunk attention: gather-on-the-fly, 64 q x 128 kv ----
__global__ void __launch_bounds__(256) k_lsh_attn(){
    extern __shared__ float sm[];
    float* sqk   = sm;                  // 128*68
    float* sv    = sm + 8704;           // 128*68
    float* sd    = sm + 17408;          // 64*128
    float* scale = sm + 25600;          // 128
    int*   skt   = (int*)(sm + 25728);  // 128
    int bh = blockIdx.x, c = blockIdx.y, tid = threadIdx.x;
    int base  = bh*8704 + c*64;
    int pbase = bh*8704 + ((c + 135) % 136)*64;
    int b = bh / 6, head = 2 + bh % 6;
    int bhh = (b<<3) + head;
    for (int p = tid; p < 128*16; p += 256){
        int row = p >> 4, v4 = p & 15;
        int src = (row < 64) ? g_st[base + row] : g_st[pbase + row - 64];
        *(float4*)&sqk[row*68 + v4*4] = ((const float4*)(g_qk + (bhh*2176 + src)*64))[v4];
        *(float4*)&sv [row*68 + v4*4] = ((const float4*)(g_v  + (bhh*2176 + src)*64))[v4];
    }
    if (tid < 128)
        skt[tid] = (tid < 64) ? g_st[base + tid] : g_st[pbase + tid - 64];
    __syncthreads();
    if (tid < 128){
        float s = 0.f;
#pragma unroll
        for (int d=0; d<64; d+=4){
            float4 v = *(float4*)&sqk[tid*68 + d];
            s += v.x*v.x + v.y*v.y + v.z*v.z + v.w*v.w;
        }
        scale[tid] = 1.0f / fmaxf(sqrtf(s), 1e-12f);
    }
    __syncthreads();
    int ty = tid >> 4, tx = tid & 15;
    int i0 = ty*4, j0 = tx*8;
    {
        float acc[4][8] = {};
        for (int d=0; d<64; d+=4){
            float4 a[4], bb[8];
#pragma unroll
            for (int i=0;i<4;i++) a[i]  = *(float4*)&sqk[(i0+i)*68 + d];
#pragma unroll
            for (int j=0;j<8;j++) bb[j] = *(float4*)&sqk[(j0+j)*68 + d];
#pragma unroll
            for (int i=0;i<4;i++)
#pragma unroll
                for (int j=0;j<8;j++){
                    acc[i][j] = fmaf(a[i].x, bb[j].x, acc[i][j]);
                    acc[i][j] = fmaf(a[i].y, bb[j].y, acc[i][j]);
                    acc[i][j] = fmaf(a[i].z, bb[j].z, acc[i][j]);
                    acc[i][j] = fmaf(a[i].w, bb[j].w, acc[i][j]);
                }
        }
#pragma unroll
        for (int i=0;i<4;i++){
            int tq = skt[i0+i];
#pragma unroll
            for (int j=0;j<8;j++){
                int tk = skt[j0+j];
                float v = acc[i][j]*scale[j0+j]*0.125f;
                if (tq < tk)       v = -1e9f;
                else if (tq == tk) v = -5e4f;
                sd[(i0+i)*128 + j0 + j] = v;
            }
        }
    }
    __syncthreads();
    {   // softmax + logsumexp per row
        int warp = tid >> 5, lane = tid & 31;
        for (int rr=0; rr<8; rr++){
            int row = warp*8 + rr;
            float d0[4];
#pragma unroll
            for (int j=0;j<4;j++) d0[j] = sd[row*128 + lane + 32*j];
            float m = fmaxf(fmaxf(d0[0],d0[1]), fmaxf(d0[2],d0[3]));
#pragma unroll
            for (int o=16;o>0;o>>=1) m = fmaxf(m, __shfl_xor_sync(0xffffffffu, m, o));
            float p[4], s = 0.f;
#pragma unroll
            for (int j=0;j<4;j++){ p[j] = expf(d0[j]-m); s += p[j]; }
#pragma unroll
            for (int o=16;o>0;o>>=1) s += __shfl_xor_sync(0xffffffffu, s, o);
            float inv = 1.0f/s;
#pragma unroll
            for (int j=0;j<4;j++) sd[row*128 + lane + 32*j] = p[j]*inv;
            if (lane == 0) g_slog[base + row] = m + logf(s);
        }
    }
    __syncthreads();
    {
        int d0 = tx*4;
        float acc[4][4] = {};
        for (int j=0; j<128; j+=4){
            float4 p[4], vv[4];
#pragma unroll
            for (int i=0;i<4;i++)    p[i]  = *(float4*)&sd[(i0+i)*128 + j];
#pragma unroll
            for (int j2=0;j2<4;j2++) vv[j2] = *(float4*)&sv[(j+j2)*68 + d0];
#pragma unroll
            for (int i=0;i<4;i++){
                acc[i][0] = fmaf(p[i].x, vv[0].x, acc[i][0]);
                acc[i][0] = fmaf(p[i].y, vv[1].x, acc[i][0]);
                acc[i][0] = fmaf(p[i].z, vv[2].x, acc[i][0]);
                acc[i][0] = fmaf(p[i].w, vv[3].x, acc[i][0]);
                acc[i][1] = fmaf(p[i].x, vv[0].y, acc[i][1]);
                acc[i][1] = fmaf(p[i].y, vv[1].y, acc[i][1]);
                acc[i][1] = fmaf(p[i].z, vv[2].y, acc[i][1]);
                acc[i][1] = fmaf(p[i].w, vv[3].y, acc[i][1]);
                acc[i][2] = fmaf(p[i].x, vv[0].z, acc[i][2]);
                acc[i][2] = fmaf(p[i].y, vv[1].z, acc[i][2]);
                acc[i][2] = fmaf(p[i].z, vv[2].z, acc[i][2]);
                acc[i][2] = fmaf(p[i].w, vv[3].z, acc[i][2]);
                acc[i][3] = fmaf(p[i].x, vv[0].w, acc[i][3]);
                acc[i][3] = fmaf(p[i].y, vv[1].w, acc[i][3]);
                acc[i][3] = fmaf(p[i].z, vv[2].w, acc[i][3]);
                acc[i][3] = fmaf(p[i].w, vv[3].w, acc[i][3]);
            }
        }
#pragma unroll
        for (int i=0;i<4;i++)
#pragma unroll
            for (int d=0;d<4;d++) g_so[(base + i0 + i)*64 + d0 + d] = acc[i][d];
    }
}

// ---- unsort + multi-hash combine, write merged matrix directly ----
__global__ void __launch_bounds__(64) k_unsort(){
    int t = blockIdx.x, bh = blockIdx.y, d = threadIdx.x;   // t < 2048 only
    __shared__ int pos[4]; __shared__ float w[4];
    if (d < 4){
        int p = g_undo[bh*8704 + d*2176 + t];
        pos[d] = p; w[d] = g_slog[bh*8704 + p];
    }
    __syncthreads();
    if (d == 0){
        float m = fmaxf(fmaxf(w[0],w[1]), fmaxf(w[2],w[3]));
        float s = 0.f;
        for (int h=0;h<4;h++){ w[h] = expf(w[h]-m); s += w[h]; }
        float inv = 1.0f/s;
        for (int h=0;h<4;h++) w[h] *= inv;
    }
    __syncthreads();
    float o = 0.f;
    for (int h=0;h<4;h++) o += w[h]*g_so[(bh*8704 + pos[h])*64 + d];
    int b = bh / 6, head = 2 + bh % 6;
    g_am[(b*2048 + t)*512 + head*64 + d] = o;
}

// ---- local windowed attention: 64 q x 256 kv, 256 threads ----
__global__ void __launch_bounds__(256) k_local_attn(){
    extern __shared__ float sm[];
    float* skv   = sm;            // 256*68 (0-127 prev win, 128-255 own)
    float* sv    = sm + 17408;    // 256*68
    float* sd    = sm + 34816;    // 64*256
    float* scale = sm + 51200;    // 256
    int bh = blockIdx.x, b = bh >> 1, head = bh & 1;
    int win = blockIdx.y, half = blockIdx.z;
    int tid = threadIdx.x;
    const float* qbase = g_qk + (((b<<3) + head)*2176)*64;
    const float* vbase = g_v  + (((b<<3) + head)*2176)*64;
    int q0 = win*128 + half*64;
    int qrow = 128 + half*64;
    for (int p = tid; p < 256*16; p += 256){
        int row = p >> 4, v4 = p & 15;
        float4 kv, vv;
        if (row < 128 && win == 0){
            kv = make_float4(0,0,0,0); vv = kv;
        } else {
            int t = (row < 128) ? (win-1)*128 + row : win*128 + row - 128;
            kv = ((const float4*)(qbase + t*64))[v4];
            vv = ((const float4*)(vbase + t*64))[v4];
        }
        *(float4*)&skv[row*68 + v4*4] = kv;
        *(float4*)&sv [row*68 + v4*4] = vv;
    }
    __syncthreads();
    {
        float s = 0.f;
#pragma unroll
        for (int d=0;d<64;d+=4){
            float4 v = *(float4*)&skv[tid*68 + d];
            s += v.x*v.x + v.y*v.y + v.z*v.z + v.w*v.w;
        }
        scale[tid] = 1.0f / fmaxf(sqrtf(s), 1e-12f);
    }
    __syncthreads();
    int ty = tid >> 4, tx = tid & 15;
    int i0 = ty*4;
    for (int jt=0; jt<2; jt++){
        int jb = tx*8 + jt*128;
        float acc[4][8] = {};
        for (int d=0; d<64; d+=4){
            float4 a[4], bb[8];
#pragma unroll
            for (int i=0;i<4;i++) a[i]  = *(float4*)&skv[(qrow+i0+i)*68 + d];
#pragma unroll
            for (int j=0;j<8;j++) bb[j] = *(float4*)&skv[(jb+j)*68 + d];
#pragma unroll
            for (int i=0;i<4;i++)
#pragma unroll
                for (int j=0;j<8;j++){
                    acc[i][j] = fmaf(a[i].x, bb[j].x, acc[i][j]);
                    acc[i][j] = fmaf(a[i].y, bb[j].y, acc[i][j]);
                    acc[i][j] = fmaf(a[i].z, bb[j].z, acc[i][j]);
                    acc[i][j] = fmaf(a[i].w, bb[j].w, acc[i][j]);
                }
        }
#pragma unroll
        for (int i=0;i<4;i++){
            int tq = q0 + i0 + i;
#pragma unroll
            for (int j=0;j<8;j++){
                int jc = jb + j;
                float v = acc[i][j]*scale[jc]*0.125f;
                if (jc < 128){
                    if (win == 0) v = -1e9f;
                    else {
                        int tk = (win-1)*128 + jc;
                        if (tq == tk) v = -5e4f; else if (tq < tk) v = -1e9f;
                    }
                } else {
                    int tk = win*128 + jc - 128;
                    if (tq == tk) v = -5e4f; else if (tq < tk) v = -1e9f;
                }
                sd[(i0+i)*256 + jc] = v;
            }
        }
    }
    __syncthreads();
    {
        int warp = tid >> 5, lane = tid & 31;
        for (int rr=0; rr<8; rr++){
            int row = warp*8 + rr;
            float d0[8];
#pragma unroll
            for (int j=0;j<8;j++) d0[j] = sd[row*256 + lane + 32*j];
            float m = d0[0];
#pragma unroll
            for (int j=1;j<8;j++) m = fmaxf(m, d0[j]);
#pragma unroll
            for (int o=16;o>0;o>>=1) m = fmaxf(m, __shfl_xor_sync(0xffffffffu, m, o));
            float p[8], s = 0.f;
#pragma unroll
            for (int j=0;j<8;j++){ p[j] = expf(d0[j]-m); s += p[j]; }
#pragma unroll
            for (int o=16;o>0;o>>=1) s += __shfl_xor_sync(0xffffffffu, s, o);
            float inv = 1.0f/s;
#pragma unroll
            for (int j=0;j<8;j++) sd[row*256 + lane + 32*j] = p[j]*inv;
        }
    }
    __syncthreads();
    {
        int d0 = tx*4;
        float acc[4][4] = {};
        for (int j=0; j<256; j+=4){
            float4 p[4], vv[4];
#pragma unroll
            for (int i=0;i<4;i++)    p[i]  = *(float4*)&sd[(i0+i)*256 + j];
#pragma unroll
            for (int j2=0;j2<4;j2++) vv[j2] = *(float4*)&sv[(j+j2)*68 + d0];
#pragma unroll
            for (int i=0;i<4;i++){
                acc[i][0] = fmaf(p[i].x, vv[0].x, acc[i][0]);
                acc[i][0] = fmaf(p[i].y, vv[1].x, acc[i][0]);
                acc[i][0] = fmaf(p[i].z, vv[2].x, acc[i][0]);
                acc[i][0] = fmaf(p[i].w, vv[3].x, acc[i][0]);
                acc[i][1] = fmaf(p[i].x, vv[0].y, acc[i][1]);
                acc[i][1] = fmaf(p[i].y, vv[1].y, acc[i][1]);
                acc[i][1] = fmaf(p[i].z, vv[2].y, acc[i][1]);
                acc[i][1] = fmaf(p[i].w, vv[3].y, acc[i][1]);
                acc[i][2] = fmaf(p[i].x, vv[0].z, acc[i][2]);
                acc[i][2] = fmaf(p[i].y, vv[1].z, acc[i][2]);
                acc[i][2] = fmaf(p[i].z, vv[2].z, acc[i][2]);
                acc[i][2] = fmaf(p[i].w, vv[3].z, acc[i][2]);
                acc[i][3] = fmaf(p[i].x, vv[0].w, acc[i][3]);
                acc[i][3] = fmaf(p[i].y, vv[1].w, acc[i][3]);
                acc[i][3] = fmaf(p[i].z, vv[2].w, acc[i][3]);
                acc[i][3] = fmaf(p[i].w, vv[3].w, acc[i][3]);
            }
        }
#pragma unroll
        for (int i=0;i<4;i++){
            int t = q0 + i0 + i;
            if (t < 2048)
#pragma unroll
                for (int d=0;d<4;d++)
                    g_am[(b*2048 + t)*512 + head*64 + d0 + d] = acc[i][d];
        }
    }
}

// ---- mean-pool over sequence ----
__global__ void __launch_bounds__(128) k_pool(const float* __restrict__ in, float* __restrict__ out){
    int b = blockIdx.x >> 2, sub = blockIdx.x & 3, d = threadIdx.x;
    const float* p = in + (b*2048 + sub)*128 + d;
    float s = 0.f;
    for (int i=0;i<512;i++) s += p[i*512];
    out[b*512 + sub*128 + d] = s * (1.0f/512.0f);
}

extern "C" void kernel_launch(void* const* d_in, const int* in_sizes, int n_in,
                              void* d_out, int out_size){
    const float* features  = (const float*)d_in[0];
    const float* w_qk      = (const float*)d_in[1];
    const float* w_v       = (const float*)d_in[2];
    const float* mem_kv    = (const float*)d_in[3];
    const float* w_out     = (const float*)d_in[4];
    const float* b_out     = (const float*)d_in[5];
    const float* ln1_g     = (const float*)d_in[6];
    const float* ln1_b     = (const float*)d_in[7];
    const float* ff_w1     = (const float*)d_in[8];
    const float* ff_b1     = (const float*)d_in[9];
    const float* ff_w2     = (const float*)d_in[10];
    const float* ff_b2     = (const float*)d_in[11];
    const float* ln2_g     = (const float*)d_in[12];
    const float* ln2_b     = (const float*)d_in[13];
    const float* lnf_g     = (const float*)d_in[14];
    const float* lnf_b     = (const float*)d_in[15];
    const float* rotations = (const float*)d_in[16];
    float* out = (float*)d_out;

    float *x1,*x2,*ain,*aq,*am,*qk,*vv,*ff;
    cudaGetSymbolAddress((void**)&x1,  g_x1);
    cudaGetSymbolAddress((void**)&x2,  g_x2);
    cudaGetSymbolAddress((void**)&ain, g_ain);
    cudaGetSymbolAddress((void**)&aq,  g_aq);
    cudaGetSymbolAddress((void**)&am,  g_am);
    cudaGetSymbolAddress((void**)&qk,  g_qk);
    cudaGetSymbolAddress((void**)&vv,  g_v);
    cudaGetSymbolAddress((void**)&ff,  g_ff);

    const int LSH_SMEM = 103424;
    const int LOC_SMEM = 205824;
    cudaFuncSetAttribute(k_lsh_attn,   cudaFuncAttributeMaxDynamicSharedMemorySize, LSH_SMEM);
    cudaFuncSetAttribute(k_local_attn, cudaFuncAttributeMaxDynamicSharedMemorySize, LOC_SMEM);

    k_embed<<<8192, 256>>>(features);

    for (int i = 0; i < 2; i++){
        k_layernorm<<<16384,128>>>(x2, (const float*)0, aq, ln1_g + i*128, ln1_b + i*128, 1);
        k_memfill<<<128,256>>>(mem_kv + i*128*128);
        EQKV eq; eq.out = qk;
        EQKV ev; ev.out = vv;
        k_gemm<<<dim3(4,272),256>>>(aq, 128, w_qk + i*128*512, 512, eq);
        k_gemm<<<dim3(4,272),256>>>(aq, 128, w_v  + i*128*512, 512, ev);
        k_local_attn<<<dim3(16,17,2),256,LOC_SMEM>>>();
        k_buckets<<<dim3(48,17),128>>>(rotations + i*64*4*17);
        k_sort<<<48,64>>>();
        k_lsh_attn<<<dim3(48,136),256,LSH_SMEM>>>();
        k_unsort<<<dim3(2048,48),64>>>();
        EAddBias e1; e1.out = x1; e1.bias = b_out + i*128; e1.ld = 128;
        k_gemm<<<dim3(1,256),256>>>(am, 512, w_out + i*512*128, 128, e1);
        k_layernorm<<<16384,128>>>(x1, (const float*)0, ain, ln2_g + i*128, ln2_b + i*128, 0);
        EGelu eg; eg.out = ff; eg.bias = ff_b1 + i*512;
        k_gemm<<<dim3(4,256),256>>>(ain, 128, ff_w1 + i*128*512, 512, eg);
        EAddBias e2; e2.out = x2; e2.bias = ff_b2 + i*128; e2.ld = 128;
        k_gemm<<<dim3(1,256),256>>>(ff, 512, ff_w2 + i*512*128, 128, e2);
    }
    k_layernorm<<<16384,128>>>(x1, x2, ain, lnf_g, lnf_b, 0);
    k_pool<<<32,128>>>(ain, out);
}

// round 8
// speedup vs baseline: 1.1286x; 1.0365x over previous
#include <cuda_runtime.h>
#include <math.h>

// B=8 S=512 FDIM=512 SUB=4 DIM=128 HEADS=8 DH=64 INNER=512
// T=2176 (2048+128 mem), NB=34, N_HASHES=4, BUCKET=64, C=136, 4T=8704

__device__ float g_x1 [8*2048*128];
__device__ float g_x2 [8*2048*128];
__device__ float g_ain[8*2048*128];
__device__ float g_aq [8*2176*128];    // packed qkv GEMM input
__device__ float g_am [8*2048*512];    // merged attention output (row-major)
__device__ float g_qk [8*8*2176*64];
__device__ float g_v  [8*8*2176*64];
__device__ int   g_bkt [48*8704];
__device__ int   g_st  [48*8704];
__device__ int   g_undo[48*8704];
__device__ float g_so  [48*8704*64];
__device__ float g_slog[48*8704];
__device__ float g_ff  [8*2048*512];

// ---- embed: features + positional encoding, init both streams ----
__global__ void __launch_bounds__(256) k_embed(const float* __restrict__ feat){
    int idx = blockIdx.x*256 + threadIdx.x;          // 8*2048*128
    int b = idx >> 18, r = idx & 262143;
    int t = r >> 7, d = r & 127;
    int s = t >> 2, f = ((t & 3) << 7) + d;
    float inv = expf(-(2.0f*(float)f/512.0f)*9.210340371976184f);
    float ang = (float)s * inv;
    float pe = (f & 1) ? cosf(ang) : sinf(ang);
    float v = feat[(b*512 + s)*512 + f] + pe;
    g_x1[idx] = v; g_x2[idx] = v;
}

// ---- layernorm over 128; pack!=0 remaps rows b*2048+t -> b*2176+t ----
__global__ void __launch_bounds__(128) k_layernorm(const float* __restrict__ in1,
                                                   const float* __restrict__ in2,
                                                   float* __restrict__ outp,
                                                   const float* __restrict__ gam,
                                                   const float* __restrict__ bet,
                                                   int pack){
    int row = blockIdx.x, d = threadIdx.x;
    float x = in1[row*128 + d];
    if (in2) x = 0.5f*(x + in2[row*128 + d]);
    __shared__ float sh[4];
    float s = x;
#pragma unroll
    for (int o=16;o>0;o>>=1) s += __shfl_xor_sync(0xffffffffu, s, o);
    if ((d & 31) == 0) sh[d>>5] = s;
    __syncthreads();
    float mean = (sh[0]+sh[1]+sh[2]+sh[3]) * (1.0f/128.0f);
    float c = x - mean;
    __syncthreads();
    float v = c*c;
#pragma unroll
    for (int o=16;o>0;o>>=1) v += __shfl_xor_sync(0xffffffffu, v, o);
    if ((d & 31) == 0) sh[d>>5] = v;
    __syncthreads();
    float var = (sh[0]+sh[1]+sh[2]+sh[3]) * (1.0f/128.0f);
    int orow = pack ? row + (row>>11)*128 : row;
    outp[orow*128 + d] = c * rsqrtf(var + 1e-5f) * gam[d] + bet[d];
}

// ---- fill mem rows of packed qkv input ----
__global__ void __launch_bounds__(256) k_memfill(const float* __restrict__ mem){
    int idx = blockIdx.x*256 + threadIdx.x;          // 8*128*128/4 float4
    int b = idx >> 12, r = idx & 4095;
    float4 v = ((const float4*)mem)[r];
    ((float4*)(g_aq + (b*2176 + 2048)*128))[r] = v;
}

// ---- GEMM: 128x128 tiles, 8x8 micro-tile, double-buffered ----
struct EQKV {
    float* out;
    __device__ __forceinline__ void operator()(int m, int n, float v) const {
        int b = m / 2176, t = m - b*2176;
        out[(((b<<3) + (n>>6))*2176 + t)*64 + (n & 63)] = v;
    }
};
struct EAddBias {
    float* out; const float* bias; int ld;
    __device__ __forceinline__ void operator()(int m, int n, float v) const {
        out[m*ld + n] += v + bias[n];
    }
};
struct EGelu {
    float* out; const float* bias;
    __device__ __forceinline__ void operator()(int m, int n, float v) const {
        float h = v + bias[n];
        out[m*512 + n] = 0.5f*h*(1.0f + erff(h*0.7071067811865475f));
    }
};

template<class EP>
__global__ void __launch_bounds__(256) k_gemm(const float* __restrict__ A, int K,
                                              const float* __restrict__ Bm, int N,
                                              EP ep){
    __shared__ float As[2][16][132];   // [buf][k][m]
    __shared__ float Bs[2][16][132];   // [buf][k][n]
    int bm = blockIdx.y*128, bn = blockIdx.x*128;
    int tid = threadIdx.x, tx = tid & 15, ty = tid >> 4;
    int arow = tid >> 1, aq = tid & 1;        // A: rows 0..127, float4 q = aq, aq+2
    int bkk = tid >> 4, bv = tid & 15;        // B: kk 0..15, float4 v = bv, bv+16
    float acc[8][8] = {};
    const float* Arow = A + (bm+arow)*K;
    // prologue -> buf 0
    {
        float4 a0 = *(const float4*)(Arow + aq*4);
        float4 a1 = *(const float4*)(Arow + (aq+2)*4);
        float4 b0 = *(const float4*)(Bm + bkk*N + bn + bv*4);
        float4 b1 = *(const float4*)(Bm + bkk*N + bn + bv*4 + 64);
        As[0][aq*4+0][arow] = a0.x; As[0][aq*4+1][arow] = a0.y;
        As[0][aq*4+2][arow] = a0.z; As[0][aq*4+3][arow] = a0.w;
        As[0][aq*4+8][arow] = a1.x; As[0][aq*4+9][arow] = a1.y;
        As[0][aq*4+10][arow] = a1.z; As[0][aq*4+11][arow] = a1.w;
        *(float4*)&Bs[0][bkk][bv*4]      = b0;
        *(float4*)&Bs[0][bkk][bv*4 + 64] = b1;
    }
    __syncthreads();
    int nt = K >> 4;
    for (int t = 0; t < nt; t++){
        int cur = t & 1, nxt = cur ^ 1;
        float4 na0, na1, nb0, nb1;
        if (t+1 < nt){
            int k0 = (t+1) << 4;
            na0 = *(const float4*)(Arow + k0 + aq*4);
            na1 = *(const float4*)(Arow + k0 + (aq+2)*4);
            nb0 = *(const float4*)(Bm + (k0+bkk)*N + bn + bv*4);
            nb1 = *(const float4*)(Bm + (k0+bkk)*N + bn + bv*4 + 64);
        }
#pragma unroll
        for (int kk=0;kk<16;kk++){
            float4 a0 = *(float4*)&As[cur][kk][ty*8];
            float4 a1 = *(float4*)&As[cur][kk][ty*8+4];
            float4 b0 = *(float4*)&Bs[cur][kk][tx*8];
            float4 b1 = *(float4*)&Bs[cur][kk][tx*8+4];
            float av[8] = {a0.x,a0.y,a0.z,a0.w,a1.x,a1.y,a1.z,a1.w};
            float bv2[8] = {b0.x,b0.y,b0.z,b0.w,b1.x,b1.y,b1.z,b1.w};
#pragma unroll
            for (int i=0;i<8;i++)
#pragma unroll
                for (int j=0;j<8;j++) acc[i][j] = fmaf(av[i], bv2[j], acc[i][j]);
        }
        if (t+1 < nt){
            As[nxt][aq*4+0][arow] = na0.x; As[nxt][aq*4+1][arow] = na0.y;
            As[nxt][aq*4+2][arow] = na0.z; As[nxt][aq*4+3][arow] = na0.w;
            As[nxt][aq*4+8][arow] = na1.x; As[nxt][aq*4+9][arow] = na1.y;
            As[nxt][aq*4+10][arow] = na1.z; As[nxt][aq*4+11][arow] = na1.w;
            *(float4*)&Bs[nxt][bkk][bv*4]      = nb0;
            *(float4*)&Bs[nxt][bkk][bv*4 + 64] = nb1;
            __syncthreads();
        }
    }
#pragma unroll
    for (int i=0;i<8;i++)
#pragma unroll
        for (int j=0;j<8;j++) ep(bm + ty*8 + i, bn + tx*8 + j, acc[i][j]);
}

// ---- LSH bucket assignment ----
__global__ void __launch_bounds__(128) k_buckets(const float* __restrict__ rot){
    __shared__ float srot[4352];                     // [f=64][h*17+i]
    int tid = threadIdx.x;
    for (int i = tid; i < 4352; i += 128) srot[i] = rot[i];
    __syncthreads();
    int bh = blockIdx.x, t = blockIdx.y*128 + tid;
    int b = bh / 6, head = 2 + bh % 6;
    const float* qp = g_qk + (((b<<3) + head)*2176 + t)*64;
    float rv[68];
#pragma unroll
    for (int u=0;u<68;u++) rv[u] = 0.0f;
    for (int f=0; f<64; f++){
        float qf = qp[f];
        const float* rp = &srot[f*68];
#pragma unroll
        for (int u=0;u<68;u++) rv[u] = fmaf(qf, rp[u], rv[u]);
    }
#pragma unroll
    for (int h=0; h<4; h++){
        float best = rv[h*17]; int bi = 0;
#pragma unroll
        for (int i=1;i<17;i++){ float v = rv[h*17+i]; if (v > best){ best = v; bi = i; } }
#pragma unroll
        for (int i=0;i<17;i++){ float v = -rv[h*17+i]; if (v > best){ best = v; bi = 17+i; } }
        g_bkt[bh*8704 + h*2176 + t] = bi + h*34;
    }
}

// ---- stable counting sort over 136 bins ----
__global__ void __launch_bounds__(64) k_sort(){
    __shared__ int hist[64][136];
    __shared__ int base[136];
    int bh = blockIdx.x, t = threadIdx.x;
    int* hrow = hist[t];
    for (int i=0;i<136;i++) hrow[i] = 0;
    const int* bk = g_bkt + bh*8704;
    int i0 = t*136;
    for (int i=0;i<136;i++) hrow[bk[i0+i]]++;
    __syncthreads();
    for (int c = t; c < 136; c += 64){
        int run = 0;
        for (int tt=0; tt<64; tt++){ int v = hist[tt][c]; hist[tt][c] = run; run += v; }
        base[c] = run;
    }
    __syncthreads();
    if (t == 0){
        int run = 0;
        for (int c=0;c<136;c++){ int v = base[c]; base[c] = run; run += v; }
    }
    __syncthreads();
    for (int i=0;i<136;i++){
        int idx = i0 + i, bb = bk[idx];
        int pos = base[bb] + hrow[bb]; hrow[bb]++;
        g_st  [bh*8704 + pos] = idx % 2176;
        g_undo[bh*8704 + idx] = pos;
    }
}

// ---- LSH chunk attention: gather-on-the-fly, 64 q x 128 kv ----
__global__ void __launch_bounds__(256) k_lsh_attn(){
    extern __shared__ float sm[];
    float* sqk   = sm;                  // 128*68
    float* sv    = sm + 8704;           // 128*68
    float* sd    = sm + 17408;          // 64*128
    float* scale = sm + 25600;          // 128
    int*   skt   = (int*)(sm + 25728);  // 128
    int bh = blockIdx.x, c = blockIdx.y, tid = threadIdx.x;
    int base  = bh*8704 + c*64;
    int pbase = bh*8704 + ((c + 135) % 136)*64;
    int b = bh / 6, head = 2 + bh % 6;
    int bhh = (b<<3) + head;
    for (int p = tid; p < 128*16; p += 256){
        int row = p >> 4, v4 = p & 15;
        int src = (row < 64) ? g_st[base + row] : g_st[pbase + row - 64];
        *(float4*)&sqk[row*68 + v4*4] = ((const float4*)(g_qk + (bhh*2176 + src)*64))[v4];
        *(float4*)&sv [row*68 + v4*4] = ((const float4*)(g_v  + (bhh*2176 + src)*64))[v4];
    }
    if (tid < 128)
        skt[tid] = (tid < 64) ? g_st[base + tid] : g_st[pbase + tid - 64];
    __syncthreads();
    if (tid < 128){
        float s = 0.f;
#pragma unroll
        for (int d=0; d<64; d+=4){
            float4 v = *(float4*)&sqk[tid*68 + d];
            s += v.x*v.x + v.y*v.y + v.z*v.z + v.w*v.w;
        }
        scale[tid] = 1.0f / fmaxf(sqrtf(s), 1e-12f);
    }
    __syncthreads();
    int ty = tid >> 4, tx = tid & 15;
    int i0 = ty*4, j0 = tx*8;
    {
        float acc[4][8] = {};
        for (int d=0; d<64; d+=4){
            float4 a[4], bb[8];
#pragma unroll
            for (int i=0;i<4;i++) a[i]  = *(float4*)&sqk[(i0+i)*68 + d];
#pragma unroll
            for (int j=0;j<8;j++) bb[j] = *(float4*)&sqk[(j0+j)*68 + d];
#pragma unroll
            for (int i=0;i<4;i++)
#pragma unroll
                for (int j=0;j<8;j++){
                    acc[i][j] = fmaf(a[i].x, bb[j].x, acc[i][j]);
                    acc[i][j] = fmaf(a[i].y, bb[j].y, acc[i][j]);
                    acc[i][j] = fmaf(a[i].z, bb[j].z, acc[i][j]);
                    acc[i][j] = fmaf(a[i].w, bb[j].w, acc[i][j]);
                }
        }
#pragma unroll
        for (int i=0;i<4;i++){
            int tq = skt[i0+i];
#pragma unroll
            for (int j=0;j<8;j++){
                int tk = skt[j0+j];
                float v = acc[i][j]*scale[j0+j]*0.125f;
                if (tq < tk)       v = -1e9f;
                else if (tq == tk) v = -5e4f;
                sd[(i0+i)*128 + j0 + j] = v;
            }
        }
    }
    __syncthreads();
    {   // softmax + logsumexp per row
        int warp = tid >> 5, lane = tid & 31;
        for (int rr=0; rr<8; rr++){
            int row = warp*8 + rr;
            float d0[4];
#pragma unroll
            for (int j=0;j<4;j++) d0[j] = sd[row*128 + lane + 32*j];
            float m = fmaxf(fmaxf(d0[0],d0[1]), fmaxf(d0[2],d0[3]));
#pragma unroll
            for (int o=16;o>0;o>>=1) m = fmaxf(m, __shfl_xor_sync(0xffffffffu, m, o));
            float p[4], s = 0.f;
#pragma unroll
            for (int j=0;j<4;j++){ p[j] = __expf(d0[j]-m); s += p[j]; }
#pragma unroll
            for (int o=16;o>0;o>>=1) s += __shfl_xor_sync(0xffffffffu, s, o);
            float inv = 1.0f/s;
#pragma unroll
            for (int j=0;j<4;j++) sd[row*128 + lane + 32*j] = p[j]*inv;
            if (lane == 0) g_slog[base + row] = m + __logf(s);
        }
    }
    __syncthreads();
    {
        int d0 = tx*4;
        float acc[4][4] = {};
        for (int j=0; j<128; j+=4){
            float4 p[4], vv[4];
#pragma unroll
            for (int i=0;i<4;i++)    p[i]  = *(float4*)&sd[(i0+i)*128 + j];
#pragma unroll
            for (int j2=0;j2<4;j2++) vv[j2] = *(float4*)&sv[(j+j2)*68 + d0];
#pragma unroll
            for (int i=0;i<4;i++){
                acc[i][0] = fmaf(p[i].x, vv[0].x, acc[i][0]);
                acc[i][0] = fmaf(p[i].y, vv[1].x, acc[i][0]);
                acc[i][0] = fmaf(p[i].z, vv[2].x, acc[i][0]);
                acc[i][0] = fmaf(p[i].w, vv[3].x, acc[i][0]);
                acc[i][1] = fmaf(p[i].x, vv[0].y, acc[i][1]);
                acc[i][1] = fmaf(p[i].y, vv[1].y, acc[i][1]);
                acc[i][1] = fmaf(p[i].z, vv[2].y, acc[i][1]);
                acc[i][1] = fmaf(p[i].w, vv[3].y, acc[i][1]);
                acc[i][2] = fmaf(p[i].x, vv[0].z, acc[i][2]);
                acc[i][2] = fmaf(p[i].y, vv[1].z, acc[i][2]);
                acc[i][2] = fmaf(p[i].z, vv[2].z, acc[i][2]);
                acc[i][2] = fmaf(p[i].w, vv[3].z, acc[i][2]);
                acc[i][3] = fmaf(p[i].x, vv[0].w, acc[i][3]);
                acc[i][3] = fmaf(p[i].y, vv[1].w, acc[i][3]);
                acc[i][3] = fmaf(p[i].z, vv[2].w, acc[i][3]);
                acc[i][3] = fmaf(p[i].w, vv[3].w, acc[i][3]);
            }
        }
#pragma unroll
        for (int i=0;i<4;i++)
#pragma unroll
            for (int d=0;d<4;d++) g_so[(base + i0 + i)*64 + d0 + d] = acc[i][d];
    }
}

// ---- unsort + multi-hash combine, 4 tokens per block ----
__global__ void __launch_bounds__(256) k_unsort(){
    int bh = blockIdx.y, tid = threadIdx.x;
    int g = tid >> 6, d = tid & 63;
    int t = blockIdx.x*4 + g;                 // t < 2048
    __shared__ int pos[4][4]; __shared__ float w[4][4];
    if (d < 4){
        int p = g_undo[bh*8704 + d*2176 + t];
        pos[g][d] = p; w[g][d] = g_slog[bh*8704 + p];
    }
    __syncthreads();
    if (d == 0){
        float m = fmaxf(fmaxf(w[g][0],w[g][1]), fmaxf(w[g][2],w[g][3]));
        float s = 0.f;
        for (int h=0;h<4;h++){ w[g][h] = __expf(w[g][h]-m); s += w[g][h]; }
        float inv = 1.0f/s;
        for (int h=0;h<4;h++) w[g][h] *= inv;
    }
    __syncthreads();
    float o = 0.f;
    for (int h=0;h<4;h++) o += w[g][h]*g_so[(bh*8704 + pos[g][h])*64 + d];
    int b = bh / 6, head = 2 + bh % 6;
    g_am[(b*2048 + t)*512 + head*64 + d] = o;
}

// ---- local windowed attention: 64 q x 256 kv, 256 threads ----
__global__ void __launch_bounds__(256) k_local_attn(){
    extern __shared__ float sm[];
    float* skv   = sm;            // 256*68 (0-127 prev win, 128-255 own)
    float* sv    = sm + 17408;    // 256*68
    float* sd    = sm + 34816;    // 64*256
    float* scale = sm + 51200;    // 256
    int bh = blockIdx.x, b = bh >> 1, head = bh & 1;
    int win = blockIdx.y, half = blockIdx.z;
    int tid = threadIdx.x;
    const float* qbase = g_qk + (((b<<3) + head)*2176)*64;
    const float* vbase = g_v  + (((b<<3) + head)*2176)*64;
    int q0 = win*128 + half*64;
    int qrow = 128 + half*64;
    for (int p = tid; p < 256*16; p += 256){
        int row = p >> 4, v4 = p & 15;
        float4 kv, vv;
        if (row < 128 && win == 0){
            kv = make_float4(0,0,0,0); vv = kv;
        } else {
            int t = (row < 128) ? (win-1)*128 + row : win*128 + row - 128;
            kv = ((const float4*)(qbase + t*64))[v4];
            vv = ((const float4*)(vbase + t*64))[v4];
        }
        *(float4*)&skv[row*68 + v4*4] = kv;
        *(float4*)&sv [row*68 + v4*4] = vv;
    }
    __syncthreads();
    {
        float s = 0.f;
#pragma unroll
        for (int d=0;d<64;d+=4){
            float4 v = *(float4*)&skv[tid*68 + d];
            s += v.x*v.x + v.y*v.y + v.z*v.z + v.w*v.w;
        }
        scale[tid] = 1.0f / fmaxf(sqrtf(s), 1e-12f);
    }
    __syncthreads();
    int ty = tid >> 4, tx = tid & 15;
    int i0 = ty*4;
    for (int jt=0; jt<2; jt++){
        int jb = tx*8 + jt*128;
        float acc[4][8] = {};
        for (int d=0; d<64; d+=4){
            float4 a[4], bb[8];
#pragma unroll
            for (int i=0;i<4;i++) a[i]  = *(float4*)&skv[(qrow+i0+i)*68 + d];
#pragma unroll
            for (int j=0;j<8;j++) bb[j] = *(float4*)&skv[(jb+j)*68 + d];
#pragma unroll
            for (int i=0;i<4;i++)
#pragma unroll
                for (int j=0;j<8;j++){
                    acc[i][j] = fmaf(a[i].x, bb[j].x, acc[i][j]);
                    acc[i][j] = fmaf(a[i].y, bb[j].y, acc[i][j]);
                    acc[i][j] = fmaf(a[i].z, bb[j].z, acc[i][j]);
                    acc[i][j] = fmaf(a[i].w, bb[j].w, acc[i][j]);
                }
        }
#pragma unroll
        for (int i=0;i<4;i++){
            int tq = q0 + i0 + i;
#pragma unroll
            for (int j=0;j<8;j++){
                int jc = jb + j;
                float v = acc[i][j]*scale[jc]*0.125f;
                if (jc < 128){
                    if (win == 0) v = -1e9f;
                    else {
                        int tk = (win-1)*128 + jc;
                        if (tq == tk) v = -5e4f; else if (tq < tk) v = -1e9f;
                    }
                } else {
                    int tk = win*128 + jc - 128;
                    if (tq == tk) v = -5e4f; else if (tq < tk) v = -1e9f;
                }
                sd[(i0+i)*256 + jc] = v;
            }
        }
    }
    __syncthreads();
    {
        int warp = tid >> 5, lane = tid & 31;
        for (int rr=0; rr<8; rr++){
            int row = warp*8 + rr;
            float d0[8];
#pragma unroll
            for (int j=0;j<8;j++) d0[j] = sd[row*256 + lane + 32*j];
            float m = d0[0];
#pragma unroll
            for (int j=1;j<8;j++) m = fmaxf(m, d0[j]);
#pragma unroll
            for (int o=16;o>0;o>>=1) m = fmaxf(m, __shfl_xor_sync(0xffffffffu, m, o));
            float p[8], s = 0.f;
#pragma unroll
            for (int j=0;j<8;j++){ p[j] = __expf(d0[j]-m); s += p[j]; }
#pragma unroll
            for (int o=16;o>0;o>>=1) s += __shfl_xor_sync(0xffffffffu, s, o);
            float inv = 1.0f/s;
#pragma unroll
            for (int j=0;j<8;j++) sd[row*256 + lane + 32*j] = p[j]*inv;
        }
    }
    __syncthreads();
    {
        int d0 = tx*4;
        float acc[4][4] = {};
        for (int j=0; j<256; j+=4){
            float4 p[4], vv[4];
#pragma unroll
            for (int i=0;i<4;i++)    p[i]  = *(float4*)&sd[(i0+i)*256 + j];
#pragma unroll
            for (int j2=0;j2<4;j2++) vv[j2] = *(float4*)&sv[(j+j2)*68 + d0];
#pragma unroll
            for (int i=0;i<4;i++){
                acc[i][0] = fmaf(p[i].x, vv[0].x, acc[i][0]);
                acc[i][0] = fmaf(p[i].y, vv[1].x, acc[i][0]);
                acc[i][0] = fmaf(p[i].z, vv[2].x, acc[i][0]);
                acc[i][0] = fmaf(p[i].w, vv[3].x, acc[i][0]);
                acc[i][1] = fmaf(p[i].x, vv[0].y, acc[i][1]);
                acc[i][1] = fmaf(p[i].y, vv[1].y, acc[i][1]);
                acc[i][1] = fmaf(p[i].z, vv[2].y, acc[i][1]);
                acc[i][1] = fmaf(p[i].w, vv[3].y, acc[i][1]);
                acc[i][2] = fmaf(p[i].x, vv[0].z, acc[i][2]);
                acc[i][2] = fmaf(p[i].y, vv[1].z, acc[i][2]);
                acc[i][2] = fmaf(p[i].z, vv[2].z, acc[i][2]);
                acc[i][2] = fmaf(p[i].w, vv[3].z, acc[i][2]);
                acc[i][3] = fmaf(p[i].x, vv[0].w, acc[i][3]);
                acc[i][3] = fmaf(p[i].y, vv[1].w, acc[i][3]);
                acc[i][3] = fmaf(p[i].z, vv[2].w, acc[i][3]);
                acc[i][3] = fmaf(p[i].w, vv[3].w, acc[i][3]);
            }
        }
#pragma unroll
        for (int i=0;i<4;i++){
            int t = q0 + i0 + i;
            if (t < 2048)
#pragma unroll
                for (int d=0;d<4;d++)
                    g_am[(b*2048 + t)*512 + head*64 + d0 + d] = acc[i][d];
        }
    }
}

// ---- mean-pool over sequence ----
__global__ void __launch_bounds__(128) k_pool(const float* __restrict__ in, float* __restrict__ out){
    int b = blockIdx.x >> 2, sub = blockIdx.x & 3, d = threadIdx.x;
    const float* p = in + (b*2048 + sub)*128 + d;
    float s = 0.f;
    for (int i=0;i<512;i++) s += p[i*512];
    out[b*512 + sub*128 + d] = s * (1.0f/512.0f);
}

extern "C" void kernel_launch(void* const* d_in, const int* in_sizes, int n_in,
                              void* d_out, int out_size){
    const float* features  = (const float*)d_in[0];
    const float* w_qk      = (const float*)d_in[1];
    const float* w_v       = (const float*)d_in[2];
    const float* mem_kv    = (const float*)d_in[3];
    const float* w_out     = (const float*)d_in[4];
    const float* b_out     = (const float*)d_in[5];
    const float* ln1_g     = (const float*)d_in[6];
    const float* ln1_b     = (const float*)d_in[7];
    const float* ff_w1     = (const float*)d_in[8];
    const float* ff_b1     = (const float*)d_in[9];
    const float* ff_w2     = (const float*)d_in[10];
    const float* ff_b2     = (const float*)d_in[11];
    const float* ln2_g     = (const float*)d_in[12];
    const float* ln2_b     = (const float*)d_in[13];
    const float* lnf_g     = (const float*)d_in[14];
    const float* lnf_b     = (const float*)d_in[15];
    const float* rotations = (const float*)d_in[16];
    float* out = (float*)d_out;

    float *x1,*x2,*ain,*aq,*am,*qk,*vv,*ff;
    cudaGetSymbolAddress((void**)&x1,  g_x1);
    cudaGetSymbolAddress((void**)&x2,  g_x2);
    cudaGetSymbolAddress((void**)&ain, g_ain);
    cudaGetSymbolAddress((void**)&aq,  g_aq);
    cudaGetSymbolAddress((void**)&am,  g_am);
    cudaGetSymbolAddress((void**)&qk,  g_qk);
    cudaGetSymbolAddress((void**)&vv,  g_v);
    cudaGetSymbolAddress((void**)&ff,  g_ff);

    const int LSH_SMEM = 103424;
    const int LOC_SMEM = 205824;
    cudaFuncSetAttribute(k_lsh_attn,   cudaFuncAttributeMaxDynamicSharedMemorySize, LSH_SMEM);
    cudaFuncSetAttribute(k_local_attn, cudaFuncAttributeMaxDynamicSharedMemorySize, LOC_SMEM);

    k_embed<<<8192, 256>>>(features);

    for (int i = 0; i < 2; i++){
        k_layernorm<<<16384,128>>>(x2, (const float*)0, aq, ln1_g + i*128, ln1_b + i*128, 1);
        k_memfill<<<128,256>>>(mem_kv + i*128*128);
        EQKV eq; eq.out = qk;
        EQKV ev; ev.out = vv;
        k_gemm<<<dim3(4,136),256>>>(aq, 128, w_qk + i*128*512, 512, eq);
        k_gemm<<<dim3(4,136),256>>>(aq, 128, w_v  + i*128*512, 512, ev);
        k_local_attn<<<dim3(16,17,2),256,LOC_SMEM>>>();
        k_buckets<<<dim3(48,17),128>>>(rotations + i*64*4*17);
        k_sort<<<48,64>>>();
        k_lsh_attn<<<dim3(48,136),256,LSH_SMEM>>>();
        k_unsort<<<dim3(512,48),256>>>();
        EAddBias e1; e1.out = x1; e1.bias = b_out + i*128; e1.ld = 128;
        k_gemm<<<dim3(1,128),256>>>(am, 512, w_out + i*512*128, 128, e1);
        k_layernorm<<<16384,128>>>(x1, (const float*)0, ain, ln2_g + i*128, ln2_b + i*128, 0);
        EGelu eg; eg.out = ff; eg.bias = ff_b1 + i*512;
        k_gemm<<<dim3(4,128),256>>>(ain, 128, ff_w1 + i*128*512, 512, eg);
        EAddBias e2; e2.out = x2; e2.bias = ff_b2 + i*128; e2.ld = 128;
        k_gemm<<<dim3(1,128),256>>>(ff, 512, ff_w2 + i*512*128, 128, e2);
    }
    k_layernorm<<<16384,128>>>(x1, x2, ain, lnf_g, lnf_b, 0);
    k_pool<<<32,128>>>(ain, out);
}

// round 11
// speedup vs baseline: 1.1802x; 1.0457x over previous
#include <cuda_runtime.h>
#include <cuda_bf16.h>
#include <math.h>
#include <stdint.h>

// B=8 S=512 FDIM=512 SUB=4 DIM=128 HEADS=8 DH=64 INNER=512
// T=2176 (2048+128 mem), NB=34, N_HASHES=4, BUCKET=64, C=136, 4T=8704

__device__ float g_x1 [8*2048*128];
__device__ float g_x2 [8*2048*128];
__device__ float g_fin[8*2048*128];
__device__ float g_aq [8*2176*128];              // fp32 qkv GEMM input (feeds buckets!)
__device__ __nv_bfloat16 g_ain[8*2048*128];      // bf16 ff1 input
__device__ __nv_bfloat16 g_am [8*2048*512];      // bf16 merged attention output
__device__ __nv_bfloat16 g_ff [8*2048*512];      // bf16 gelu output
__device__ float g_qk [8*8*2176*64];
__device__ float g_v  [8*8*2176*64];
__device__ int   g_bkt [48*8704];
__device__ int   g_st  [48*8704];
__device__ int   g_undo[48*8704];
__device__ float g_so  [48*8704*64];
__device__ float g_slog[48*8704];
__device__ __nv_bfloat16 g_wt_out[2][128*512];   // w_out^T  [n=128][k=512]
__device__ __nv_bfloat16 g_wt_ff1[2][512*128];   // ff_w1^T  [n=512][k=128]
__device__ __nv_bfloat16 g_wt_ff2[2][128*512];   // ff_w2^T  [n=128][k=512]

__device__ __forceinline__ uint32_t smem_u32(const void* p){
    uint32_t a;
    asm("{ .reg .u64 t; cvta.to.shared.u64 t, %1; cvt.u32.u64 %0, t; }" : "=r"(a) : "l"(p));
    return a;
}
__device__ __forceinline__ void ldm4(uint32_t& r0, uint32_t& r1, uint32_t& r2, uint32_t& r3,
                                     uint32_t addr){
    asm volatile("ldmatrix.sync.aligned.m8n8.x4.shared.b16 {%0,%1,%2,%3}, [%4];"
        : "=r"(r0),"=r"(r1),"=r"(r2),"=r"(r3) : "r"(addr));
}
__device__ __forceinline__ void mma16816(float* c, const uint32_t* a, const uint32_t* b){
    asm volatile("mma.sync.aligned.m16n8k16.row.col.f32.bf16.bf16.f32 "
        "{%0,%1,%2,%3}, {%4,%5,%6,%7}, {%8,%9}, {%0,%1,%2,%3};"
        : "+f"(c[0]),"+f"(c[1]),"+f"(c[2]),"+f"(c[3])
        : "r"(a[0]),"r"(a[1]),"r"(a[2]),"r"(a[3]), "r"(b[0]),"r"(b[1]));
}

// ---- weight convert+transpose: in fp32 [K][N] -> out bf16 [N][K] ----
__global__ void __launch_bounds__(256) k_wcvt(const float* __restrict__ in,
                                              __nv_bfloat16* __restrict__ out,
                                              int K, int N){
    int idx = blockIdx.x*256 + threadIdx.x;          // N*K
    int n = idx / K, k = idx - n*K;
    out[idx] = __float2bfloat16(in[k*N + n]);
}

// ====== HMMA GEMM: C[M,N] = A[M,K](bf16) * BT[N,K]^T, fp32 epilogue ======
struct EAddBias {
    float* out; const float* bias; int ld;
    __device__ __forceinline__ void operator()(int m, int n, float v) const {
        out[m*ld + n] += v + bias[n];
    }
};
struct EGelu {
    __nv_bfloat16* out; const float* bias;
    __device__ __forceinline__ void operator()(int m, int n, float v) const {
        float h = v + bias[n];
        out[m*512 + n] = __float2bfloat16(0.5f*h*(1.0f + erff(h*0.7071067811865475f)));
    }
};

template<class EP>
__global__ void __launch_bounds__(256) k_tgemm(const __nv_bfloat16* __restrict__ A, int K,
                                               const __nv_bfloat16* __restrict__ BT,
                                               EP ep){
    __shared__ __nv_bfloat16 As[128][72];
    __shared__ __nv_bfloat16 Bs[128][72];
    int tid = threadIdx.x, wid = tid >> 5, lane = tid & 31;
    int wm = wid >> 1, wn = wid & 1;          // warps 4(m) x 2(n): warp tile 32x64
    int bm = blockIdx.y*128, bn = blockIdx.x*128;
    float acc[2][8][4] = {};
    int nc = K >> 6;                          // K chunks of 64
    for (int kc = 0; kc < nc; kc++){
        for (int p = tid; p < 1024; p += 256){
            int row = p >> 3, q = p & 7;      // 8 bf16 (16B) each
            *(uint4*)&As[row][q*8] = *(const uint4*)(A  + (size_t)(bm+row)*K + kc*64 + q*8);
            *(uint4*)&Bs[row][q*8] = *(const uint4*)(BT + (size_t)(bn+row)*K + kc*64 + q*8);
        }
        __syncthreads();
#pragma unroll
        for (int s = 0; s < 4; s++){          // 4 k16 steps
            uint32_t af[2][4];
#pragma unroll
            for (int mt = 0; mt < 2; mt++){
                uint32_t addr = smem_u32(&As[wm*32 + mt*16 + (lane & 15)][s*16 + (lane >> 4)*8]);
                ldm4(af[mt][0], af[mt][1], af[mt][2], af[mt][3], addr);
            }
            uint32_t bf[8][2];
#pragma unroll
            for (int nt16 = 0; nt16 < 4; nt16++){
                int mi = lane >> 3;
                uint32_t addr = smem_u32(&Bs[wn*64 + nt16*16 + (mi >> 1)*8 + (lane & 7)][s*16 + (mi & 1)*8]);
                uint32_t r0,r1,r2,r3;
                ldm4(r0,r1,r2,r3, addr);
                bf[nt16*2][0]   = r0; bf[nt16*2][1]   = r1;
                bf[nt16*2+1][0] = r2; bf[nt16*2+1][1] = r3;
            }
#pragma unroll
            for (int mt = 0; mt < 2; mt++)
#pragma unroll
                for (int nt = 0; nt < 8; nt++)
                    mma16816(acc[mt][nt], af[mt], bf[nt]);
        }
        __syncthreads();
    }
#pragma unroll
    for (int mt = 0; mt < 2; mt++){
#pragma unroll
        for (int nt = 0; nt < 8; nt++){
            int m = bm + wm*32 + mt*16 + (lane >> 2);
            int n = bn + wn*64 + nt*8 + (lane & 3)*2;
            ep(m,   n,   acc[mt][nt][0]);
            ep(m,   n+1, acc[mt][nt][1]);
            ep(m+8, n,   acc[mt][nt][2]);
            ep(m+8, n+1, acc[mt][nt][3]);
        }
    }
}

// ================= rest of pipeline =================
__global__ void __launch_bounds__(256) k_embed(const float* __restrict__ feat){
    int idx = blockIdx.x*256 + threadIdx.x;
    int b = idx >> 18, r = idx & 262143;
    int t = r >> 7, d = r & 127;
    int s = t >> 2, f = ((t & 3) << 7) + d;
    float inv = expf(-(2.0f*(float)f/512.0f)*9.210340371976184f);
    float ang = (float)s * inv;
    float pe = (f & 1) ? cosf(ang) : sinf(ang);
    float v = feat[(b*512 + s)*512 + f] + pe;
    g_x1[idx] = v; g_x2[idx] = v;
}

template<typename OutT>
__global__ void __launch_bounds__(128) k_layernorm(const float* __restrict__ in1,
                                                   const float* __restrict__ in2,
                                                   OutT* __restrict__ outp,
                                                   const float* __restrict__ gam,
                                                   const float* __restrict__ bet,
                                                   int pack){
    int row = blockIdx.x, d = threadIdx.x;
    float x = in1[row*128 + d];
    if (in2) x = 0.5f*(x + in2[row*128 + d]);
    __shared__ float sh[4];
    float s = x;
#pragma unroll
    for (int o=16;o>0;o>>=1) s += __shfl_xor_sync(0xffffffffu, s, o);
    if ((d & 31) == 0) sh[d>>5] = s;
    __syncthreads();
    float mean = (sh[0]+sh[1]+sh[2]+sh[3]) * (1.0f/128.0f);
    float c = x - mean;
    __syncthreads();
    float v = c*c;
#pragma unroll
    for (int o=16;o>0;o>>=1) v += __shfl_xor_sync(0xffffffffu, v, o);
    if ((d & 31) == 0) sh[d>>5] = v;
    __syncthreads();
    float var = (sh[0]+sh[1]+sh[2]+sh[3]) * (1.0f/128.0f);
    int orow = pack ? row + (row>>11)*128 : row;
    outp[orow*128 + d] = (OutT)(c * rsqrtf(var + 1e-5f) * gam[d] + bet[d]);
}

__global__ void __launch_bounds__(256) k_memfill(const float* __restrict__ mem){
    int idx = blockIdx.x*256 + threadIdx.x;
    int b = idx >> 12, r = idx & 4095;
    float4 v = ((const float4*)mem)[r];
    ((float4*)(g_aq + (b*2176 + 2048)*128))[r] = v;
}

// fp32 GEMM (qkv only — feeds LSH argmax, must stay fp32)
struct EQKV {
    float* out;
    __device__ __forceinline__ void operator()(int m, int n, float v) const {
        int b = m / 2176, t = m - b*2176;
        out[(((b<<3) + (n>>6))*2176 + t)*64 + (n & 63)] = v;
    }
};
template<class EP>
__global__ void __launch_bounds__(256) k_gemm(const float* __restrict__ A, int K,
                                              const float* __restrict__ Bm, int N,
                                              EP ep){
    __shared__ float As[2][16][132];
    __shared__ float Bs[2][16][132];
    int bm = blockIdx.y*128, bn = blockIdx.x*128;
    int tid = threadIdx.x, tx = tid & 15, ty = tid >> 4;
    int arow = tid >> 1, aq = tid & 1;
    int bkk = tid >> 4, bv = tid & 15;
    float acc[8][8] = {};
    const float* Arow = A + (bm+arow)*K;
    {
        float4 a0 = *(const float4*)(Arow + aq*4);
        float4 a1 = *(const float4*)(Arow + (aq+2)*4);
        float4 b0 = *(const float4*)(Bm + bkk*N + bn + bv*4);
        float4 b1 = *(const float4*)(Bm + bkk*N + bn + bv*4 + 64);
        As[0][aq*4+0][arow] = a0.x; As[0][aq*4+1][arow] = a0.y;
        As[0][aq*4+2][arow] = a0.z; As[0][aq*4+3][arow] = a0.w;
        As[0][aq*4+8][arow] = a1.x; As[0][aq*4+9][arow] = a1.y;
        As[0][aq*4+10][arow] = a1.z; As[0][aq*4+11][arow] = a1.w;
        *(float4*)&Bs[0][bkk][bv*4]      = b0;
        *(float4*)&Bs[0][bkk][bv*4 + 64] = b1;
    }
    __syncthreads();
    int nt = K >> 4;
    for (int t = 0; t < nt; t++){
        int cur = t & 1, nxt = cur ^ 1;
        float4 na0, na1, nb0, nb1;
        if (t+1 < nt){
            int k0 = (t+1) << 4;
            na0 = *(const float4*)(Arow + k0 + aq*4);
            na1 = *(const float4*)(Arow + k0 + (aq+2)*4);
            nb0 = *(const float4*)(Bm + (k0+bkk)*N + bn + bv*4);
            nb1 = *(const float4*)(Bm + (k0+bkk)*N + bn + bv*4 + 64);
        }
#pragma unroll
        for (int kk=0;kk<16;kk++){
            float4 a0 = *(float4*)&As[cur][kk][ty*8];
            float4 a1 = *(float4*)&As[cur][kk][ty*8+4];
            float4 b0 = *(float4*)&Bs[cur][kk][tx*8];
            float4 b1 = *(float4*)&Bs[cur][kk][tx*8+4];
            float av[8] = {a0.x,a0.y,a0.z,a0.w,a1.x,a1.y,a1.z,a1.w};
            float bv2[8] = {b0.x,b0.y,b0.z,b0.w,b1.x,b1.y,b1.z,b1.w};
#pragma unroll
            for (int i=0;i<8;i++)
#pragma unroll
                for (int j=0;j<8;j++) acc[i][j] = fmaf(av[i], bv2[j], acc[i][j]);
        }
        if (t+1 < nt){
            As[nxt][aq*4+0][arow] = na0.x; As[nxt][aq*4+1][arow] = na0.y;
            As[nxt][aq*4+2][arow] = na0.z; As[nxt][aq*4+3][arow] = na0.w;
            As[nxt][aq*4+8][arow] = na1.x; As[nxt][aq*4+9][arow] = na1.y;
            As[nxt][aq*4+10][arow] = na1.z; As[nxt][aq*4+11][arow] = na1.w;
            *(float4*)&Bs[nxt][bkk][bv*4]      = nb0;
            *(float4*)&Bs[nxt][bkk][bv*4 + 64] = nb1;
            __syncthreads();
        }
    }
#pragma unroll
    for (int i=0;i<8;i++)
#pragma unroll
        for (int j=0;j<8;j++) ep(bm + ty*8 + i, bn + tx*8 + j, acc[i][j]);
}

__global__ void __launch_bounds__(128) k_buckets(const float* __restrict__ rot){
    __shared__ float srot[4352];
    int tid = threadIdx.x;
    for (int i = tid; i < 4352; i += 128) srot[i] = rot[i];
    __syncthreads();
    int bh = blockIdx.x, t = blockIdx.y*128 + tid;
    int b = bh / 6, head = 2 + bh % 6;
    const float* qp = g_qk + (((b<<3) + head)*2176 + t)*64;
    float rv[68];
#pragma unroll
    for (int u=0;u<68;u++) rv[u] = 0.0f;
    for (int f=0; f<64; f++){
        float qf = qp[f];
        const float* rp = &srot[f*68];
#pragma unroll
        for (int u=0;u<68;u++) rv[u] = fmaf(qf, rp[u], rv[u]);
    }
#pragma unroll
    for (int h=0; h<4; h++){
        float best = rv[h*17]; int bi = 0;
#pragma unroll
        for (int i=1;i<17;i++){ float v = rv[h*17+i]; if (v > best){ best = v; bi = i; } }
#pragma unroll
        for (int i=0;i<17;i++){ float v = -rv[h*17+i]; if (v > best){ best = v; bi = 17+i; } }
        g_bkt[bh*8704 + h*2176 + t] = bi + h*34;
    }
}

__global__ void __launch_bounds__(64) k_sort(){
    __shared__ int hist[64][136];
    __shared__ int base[136];
    int bh = blockIdx.x, t = threadIdx.x;
    int* hrow = hist[t];
    for (int i=0;i<136;i++) hrow[i] = 0;
    const int* bk = g_bkt + bh*8704;
    int i0 = t*136;
    for (int i=0;i<136;i++) hrow[bk[i0+i]]++;
    __syncthreads();
    for (int c = t; c < 136; c += 64){
        int run = 0;
        for (int tt=0; tt<64; tt++){ int v = hist[tt][c]; hist[tt][c] = run; run += v; }
        base[c] = run;
    }
    __syncthreads();
    if (t == 0){
        int run = 0;
        for (int c=0;c<136;c++){ int v = base[c]; base[c] = run; run += v; }
    }
    __syncthreads();
    for (int i=0;i<136;i++){
        int idx = i0 + i, bb = bk[idx];
        int pos = base[bb] + hrow[bb]; hrow[bb]++;
        g_st  [bh*8704 + pos] = idx % 2176;
        g_undo[bh*8704 + idx] = pos;
    }
}

__global__ void __launch_bounds__(256) k_lsh_attn(){
    extern __shared__ float sm[];
    float* sqk   = sm;
    float* sv    = sm + 8704;
    float* sd    = sm + 17408;
    float* scale = sm + 25600;
    int*   skt   = (int*)(sm + 25728);
    int bh = blockIdx.x, c = blockIdx.y, tid = threadIdx.x;
    int base  = bh*8704 + c*64;
    int pbase = bh*8704 + ((c + 135) % 136)*64;
    int b = bh / 6, head = 2 + bh % 6;
    int bhh = (b<<3) + head;
    for (int p = tid; p < 128*16; p += 256){
        int row = p >> 4, v4 = p & 15;
        int src = (row < 64) ? g_st[base + row] : g_st[pbase + row - 64];
        *(float4*)&sqk[row*68 + v4*4] = ((const float4*)(g_qk + (bhh*2176 + src)*64))[v4];
        *(float4*)&sv [row*68 + v4*4] = ((const float4*)(g_v  + (bhh*2176 + src)*64))[v4];
    }
    if (tid < 128)
        skt[tid] = (tid < 64) ? g_st[base + tid] : g_st[pbase + tid - 64];
    __syncthreads();
    if (tid < 128){
        float s = 0.f;
#pragma unroll
        for (int d=0; d<64; d+=4){
            float4 v = *(float4*)&sqk[tid*68 + d];
            s += v.x*v.x + v.y*v.y + v.z*v.z + v.w*v.w;
        }
        scale[tid] = 1.0f / fmaxf(sqrtf(s), 1e-12f);
    }
    __syncthreads();
    int ty = tid >> 4, tx = tid & 15;
    int i0 = ty*4, j0 = tx*8;
    {
        float acc[4][8] = {};
        for (int d=0; d<64; d+=4){
            float4 a[4], bb[8];
#pragma unroll
            for (int i=0;i<4;i++) a[i]  = *(float4*)&sqk[(i0+i)*68 + d];
#pragma unroll
            for (int j=0;j<8;j++) bb[j] = *(float4*)&sqk[(j0+j)*68 + d];
#pragma unroll
            for (int i=0;i<4;i++)
#pragma unroll
                for (int j=0;j<8;j++){
                    acc[i][j] = fmaf(a[i].x, bb[j].x, acc[i][j]);
                    acc[i][j] = fmaf(a[i].y, bb[j].y, acc[i][j]);
                    acc[i][j] = fmaf(a[i].z, bb[j].z, acc[i][j]);
                    acc[i][j] = fmaf(a[i].w, bb[j].w, acc[i][j]);
                }
        }
#pragma unroll
        for (int i=0;i<4;i++){
            int tq = skt[i0+i];
#pragma unroll
            for (int j=0;j<8;j++){
                int tk = skt[j0+j];
                float v = acc[i][j]*scale[j0+j]*0.125f;
                if (tq < tk)       v = -1e9f;
                else if (tq == tk) v = -5e4f;
                sd[(i0+i)*128 + j0 + j] = v;
            }
        }
    }
    __syncthreads();
    {
        int warp = tid >> 5, lane = tid & 31;
        for (int rr=0; rr<8; rr++){
            int row = warp*8 + rr;
            float d0[4];
#pragma unroll
            for (int j=0;j<4;j++) d0[j] = sd[row*128 + lane + 32*j];
            float m = fmaxf(fmaxf(d0[0],d0[1]), fmaxf(d0[2],d0[3]));
#pragma unroll
            for (int o=16;o>0;o>>=1) m = fmaxf(m, __shfl_xor_sync(0xffffffffu, m, o));
            float p[4], s = 0.f;
#pragma unroll
            for (int j=0;j<4;j++){ p[j] = __expf(d0[j]-m); s += p[j]; }
#pragma unroll
            for (int o=16;o>0;o>>=1) s += __shfl_xor_sync(0xffffffffu, s, o);
            float inv = 1.0f/s;
#pragma unroll
            for (int j=0;j<4;j++) sd[row*128 + lane + 32*j] = p[j]*inv;
            if (lane == 0) g_slog[base + row] = m + __logf(s);
        }
    }
    __syncthreads();
    {
        int d0 = tx*4;
        float acc[4][4] = {};
        for (int j=0; j<128; j+=4){
            float4 p[4], vv[4];
#pragma unroll
            for (int i=0;i<4;i++)    p[i]  = *(float4*)&sd[(i0+i)*128 + j];
#pragma unroll
            for (int j2=0;j2<4;j2++) vv[j2] = *(float4*)&sv[(j+j2)*68 + d0];
#pragma unroll
            for (int i=0;i<4;i++){
                acc[i][0] = fmaf(p[i].x, vv[0].x, acc[i][0]);
                acc[i][0] = fmaf(p[i].y, vv[1].x, acc[i][0]);
                acc[i][0] = fmaf(p[i].z, vv[2].x, acc[i][0]);
                acc[i][0] = fmaf(p[i].w, vv[3].x, acc[i][0]);
                acc[i][1] = fmaf(p[i].x, vv[0].y, acc[i][1]);
                acc[i][1] = fmaf(p[i].y, vv[1].y, acc[i][1]);
                acc[i][1] = fmaf(p[i].z, vv[2].y, acc[i][1]);
                acc[i][1] = fmaf(p[i].w, vv[3].y, acc[i][1]);
                acc[i][2] = fmaf(p[i].x, vv[0].z, acc[i][2]);
                acc[i][2] = fmaf(p[i].y, vv[1].z, acc[i][2]);
                acc[i][2] = fmaf(p[i].z, vv[2].z, acc[i][2]);
                acc[i][2] = fmaf(p[i].w, vv[3].z, acc[i][2]);
                acc[i][3] = fmaf(p[i].x, vv[0].w, acc[i][3]);
                acc[i][3] = fmaf(p[i].y, vv[1].w, acc[i][3]);
                acc[i][3] = fmaf(p[i].z, vv[2].w, acc[i][3]);
                acc[i][3] = fmaf(p[i].w, vv[3].w, acc[i][3]);
            }
        }
#pragma unroll
        for (int i=0;i<4;i++)
#pragma unroll
            for (int d=0;d<4;d++) g_so[(base + i0 + i)*64 + d0 + d] = acc[i][d];
    }
}

__global__ void __launch_bounds__(256) k_unsort(){
    int bh = blockIdx.y, tid = threadIdx.x;
    int g = tid >> 6, d = tid & 63;
    int t = blockIdx.x*4 + g;
    __shared__ int pos[4][4]; __shared__ float w[4][4];
    if (d < 4){
        int p = g_undo[bh*8704 + d*2176 + t];
        pos[g][d] = p; w[g][d] = g_slog[bh*8704 + p];
    }
    __syncthreads();
    if (d == 0){
        float m = fmaxf(fmaxf(w[g][0],w[g][1]), fmaxf(w[g][2],w[g][3]));
        float s = 0.f;
        for (int h=0;h<4;h++){ w[g][h] = __expf(w[g][h]-m); s += w[g][h]; }
        float inv = 1.0f/s;
        for (int h=0;h<4;h++) w[g][h] *= inv;
    }
    __syncthreads();
    float o = 0.f;
    for (int h=0;h<4;h++) o += w[g][h]*g_so[(bh*8704 + pos[g][h])*64 + d];
    int b = bh / 6, head = 2 + bh % 6;
    g_am[(b*2048 + t)*512 + head*64 + d] = __float2bfloat16(o);
}

__global__ void __launch_bounds__(256) k_local_attn(){
    extern __shared__ float sm[];
    float* skv   = sm;
    float* sv    = sm + 17408;
    float* sd    = sm + 34816;
    float* scale = sm + 51200;
    int bh = blockIdx.x, b = bh >> 1, head = bh & 1;
    int win = blockIdx.y, half = blockIdx.z;
    int tid = threadIdx.x;
    const float* qbase = g_qk + (((b<<3) + head)*2176)*64;
    const float* vbase = g_v  + (((b<<3) + head)*2176)*64;
    int q0 = win*128 + half*64;
    int qrow = 128 + half*64;
    for (int p = tid; p < 256*16; p += 256){
        int row = p >> 4, v4 = p & 15;
        float4 kv, vv;
        if (row < 128 && win == 0){
            kv = make_float4(0,0,0,0); vv = kv;
        } else {
            int t = (row < 128) ? (win-1)*128 + row : win*128 + row - 128;
            kv = ((const float4*)(qbase + t*64))[v4];
            vv = ((const float4*)(vbase + t*64))[v4];
        }
        *(float4*)&skv[row*68 + v4*4] = kv;
        *(float4*)&sv [row*68 + v4*4] = vv;
    }
    __syncthreads();
    {
        float s = 0.f;
#pragma unroll
        for (int d=0;d<64;d+=4){
            float4 v = *(float4*)&skv[tid*68 + d];
            s += v.x*v.x + v.y*v.y + v.z*v.z + v.w*v.w;
        }
        scale[tid] = 1.0f / fmaxf(sqrtf(s), 1e-12f);
    }
    __syncthreads();
    int ty = tid >> 4, tx = tid & 15;
    int i0 = ty*4;
    for (int jt=0; jt<2; jt++){
        int jb = tx*8 + jt*128;
        float acc[4][8] = {};
        for (int d=0; d<64; d+=4){
            float4 a[4], bb[8];
#pragma unroll
            for (int i=0;i<4;i++) a[i]  = *(float4*)&skv[(qrow+i0+i)*68 + d];
#pragma unroll
            for (int j=0;j<8;j++) bb[j] = *(float4*)&skv[(jb+j)*68 + d];
#pragma unroll
            for (int i=0;i<4;i++)
#pragma unroll
                for (int j=0;j<8;j++){
                    acc[i][j] = fmaf(a[i].x, bb[j].x, acc[i][j]);
                    acc[i][j] = fmaf(a[i].y, bb[j].y, acc[i][j]);
                    acc[i][j] = fmaf(a[i].z, bb[j].z, acc[i][j]);
                    acc[i][j] = fmaf(a[i].w, bb[j].w, acc[i][j]);
                }
        }
#pragma unroll
        for (int i=0;i<4;i++){
            int tq = q0 + i0 + i;
#pragma unroll
            for (int j=0;j<8;j++){
                int jc = jb + j;
                float v = acc[i][j]*scale[jc]*0.125f;
                if (jc < 128){
                    if (win == 0) v = -1e9f;
                    else {
                        int tk = (win-1)*128 + jc;
                        if (tq == tk) v = -5e4f; else if (tq < tk) v = -1e9f;
                    }
                } else {
                    int tk = win*128 + jc - 128;
                    if (tq == tk) v = -5e4f; else if (tq < tk) v = -1e9f;
                }
                sd[(i0+i)*256 + jc] = v;
            }
        }
    }
    __syncthreads();
    {
        int warp = tid >> 5, lane = tid & 31;
        for (int rr=0; rr<8; rr++){
            int row = warp*8 + rr;
            float d0[8];
#pragma unroll
            for (int j=0;j<8;j++) d0[j] = sd[row*256 + lane + 32*j];
            float m = d0[0];
#pragma unroll
            for (int j=1;j<8;j++) m = fmaxf(m, d0[j]);
#pragma unroll
            for (int o=16;o>0;o>>=1) m = fmaxf(m, __shfl_xor_sync(0xffffffffu, m, o));
            float p[8], s = 0.f;
#pragma unroll
            for (int j=0;j<8;j++){ p[j] = __expf(d0[j]-m); s += p[j]; }
#pragma unroll
            for (int o=16;o>0;o>>=1) s += __shfl_xor_sync(0xffffffffu, s, o);
            float inv = 1.0f/s;
#pragma unroll
            for (int j=0;j<8;j++) sd[row*256 + lane + 32*j] = p[j]*inv;
        }
    }
    __syncthreads();
    {
        int d0 = tx*4;
        float acc[4][4] = {};
        for (int j=0; j<256; j+=4){
            float4 p[4], vv[4];
#pragma unroll
            for (int i=0;i<4;i++)    p[i]  = *(float4*)&sd[(i0+i)*256 + j];
#pragma unroll
            for (int j2=0;j2<4;j2++) vv[j2] = *(float4*)&sv[(j+j2)*68 + d0];
#pragma unroll
            for (int i=0;i<4;i++){
                acc[i][0] = fmaf(p[i].x, vv[0].x, acc[i][0]);
                acc[i][0] = fmaf(p[i].y, vv[1].x, acc[i][0]);
                acc[i][0] = fmaf(p[i].z, vv[2].x, acc[i][0]);
                acc[i][0] = fmaf(p[i].w, vv[3].x, acc[i][0]);
                acc[i][1] = fmaf(p[i].x, vv[0].y, acc[i][1]);
                acc[i][1] = fmaf(p[i].y, vv[1].y, acc[i][1]);
                acc[i][1] = fmaf(p[i].z, vv[2].y, acc[i][1]);
                acc[i][1] = fmaf(p[i].w, vv[3].y, acc[i][1]);
                acc[i][2] = fmaf(p[i].x, vv[0].z, acc[i][2]);
                acc[i][2] = fmaf(p[i].y, vv[1].z, acc[i][2]);
                acc[i][2] = fmaf(p[i].z, vv[2].z, acc[i][2]);
                acc[i][2] = fmaf(p[i].w, vv[3].z, acc[i][2]);
                acc[i][3] = fmaf(p[i].x, vv[0].w, acc[i][3]);
                acc[i][3] = fmaf(p[i].y, vv[1].w, acc[i][3]);
                acc[i][3] = fmaf(p[i].z, vv[2].w, acc[i][3]);
                acc[i][3] = fmaf(p[i].w, vv[3].w, acc[i][3]);
            }
        }
#pragma unroll
        for (int i=0;i<4;i++){
            int t = q0 + i0 + i;
            if (t < 2048)
#pragma unroll
                for (int d=0;d<4;d++)
                    g_am[(b*2048 + t)*512 + head*64 + d0 + d] = __float2bfloat16(acc[i][d]);
        }
    }
}

__global__ void __launch_bounds__(128) k_pool(const float* __restrict__ in, float* __restrict__ out){
    int b = blockIdx.x >> 2, sub = blockIdx.x & 3, d = threadIdx.x;
    const float* p = in + (b*2048 + sub)*128 + d;
    float s = 0.f;
    for (int i=0;i<512;i++) s += p[i*512];
    out[b*512 + sub*128 + d] = s * (1.0f/512.0f);
}

extern "C" void kernel_launch(void* const* d_in, const int* in_sizes, int n_in,
                              void* d_out, int out_size){
    const float* features  = (const float*)d_in[0];
    const float* w_qk      = (const float*)d_in[1];
    const float* w_v       = (const float*)d_in[2];
    const float* mem_kv    = (const float*)d_in[3];
    const float* w_out     = (const float*)d_in[4];
    const float* b_out     = (const float*)d_in[5];
    const float* ln1_g     = (const float*)d_in[6];
    const float* ln1_b     = (const float*)d_in[7];
    const float* ff_w1     = (const float*)d_in[8];
    const float* ff_b1     = (const float*)d_in[9];
    const float* ff_w2     = (const float*)d_in[10];
    const float* ff_b2     = (const float*)d_in[11];
    const float* ln2_g     = (const float*)d_in[12];
    const float* ln2_b     = (const float*)d_in[13];
    const float* lnf_g     = (const float*)d_in[14];
    const float* lnf_b     = (const float*)d_in[15];
    const float* rotations = (const float*)d_in[16];
    float* out = (float*)d_out;

    float *x1,*x2,*fin,*aq,*qk,*vv;
    __nv_bfloat16 *ain,*am,*ff,*wt_out,*wt_ff1,*wt_ff2;
    cudaGetSymbolAddress((void**)&x1,  g_x1);
    cudaGetSymbolAddress((void**)&x2,  g_x2);
    cudaGetSymbolAddress((void**)&fin, g_fin);
    cudaGetSymbolAddress((void**)&aq,  g_aq);
    cudaGetSymbolAddress((void**)&qk,  g_qk);
    cudaGetSymbolAddress((void**)&vv,  g_v);
    cudaGetSymbolAddress((void**)&ain, g_ain);
    cudaGetSymbolAddress((void**)&am,  g_am);
    cudaGetSymbolAddress((void**)&ff,  g_ff);
    cudaGetSymbolAddress((void**)&wt_out, g_wt_out);
    cudaGetSymbolAddress((void**)&wt_ff1, g_wt_ff1);
    cudaGetSymbolAddress((void**)&wt_ff2, g_wt_ff2);

    const int LSH_SMEM = 103424;
    const int LOC_SMEM = 205824;
    cudaFuncSetAttribute(k_lsh_attn,   cudaFuncAttributeMaxDynamicSharedMemorySize, LSH_SMEM);
    cudaFuncSetAttribute(k_local_attn, cudaFuncAttributeMaxDynamicSharedMemorySize, LOC_SMEM);

    // pre-transpose+convert weights to bf16 [N][K]
    for (int i = 0; i < 2; i++){
        k_wcvt<<<(128*512)/256,256>>>(w_out + i*512*128, wt_out + i*128*512, 512, 128);
        k_wcvt<<<(512*128)/256,256>>>(ff_w1 + i*128*512, wt_ff1 + i*512*128, 128, 512);
        k_wcvt<<<(128*512)/256,256>>>(ff_w2 + i*512*128, wt_ff2 + i*128*512, 512, 128);
    }

    k_embed<<<8192, 256>>>(features);

    for (int i = 0; i < 2; i++){
        k_layernorm<float><<<16384,128>>>(x2, (const float*)0, aq, ln1_g + i*128, ln1_b + i*128, 1);
        k_memfill<<<128,256>>>(mem_kv + i*128*128);
        EQKV eq; eq.out = qk;
        EQKV ev; ev.out = vv;
        k_gemm<<<dim3(4,136),256>>>(aq, 128, w_qk + i*128*512, 512, eq);
        k_gemm<<<dim3(4,136),256>>>(aq, 128, w_v  + i*128*512, 512, ev);
        k_local_attn<<<dim3(16,17,2),256,LOC_SMEM>>>();
        k_buckets<<<dim3(48,17),128>>>(rotations + i*64*4*17);
        k_sort<<<48,64>>>();
        k_lsh_attn<<<dim3(48,136),256,LSH_SMEM>>>();
        k_unsort<<<dim3(512,48),256>>>();
        // y1 = x1 + am @ w_out + b_out   (HMMA)
        EAddBias e1; e1.out = x1; e1.bias = b_out + i*128; e1.ld = 128;
        k_tgemm<<<dim3(1,128),256>>>(am, 512, wt_out + i*128*512, e1);
        k_layernorm<__nv_bfloat16><<<16384,128>>>(x1, (const float*)0, ain, ln2_g + i*128, ln2_b + i*128, 0);
        // ff1 (HMMA, gelu epilogue)
        EGelu eg; eg.out = ff; eg.bias = ff_b1 + i*512;
        k_tgemm<<<dim3(4,128),256>>>(ain, 128, wt_ff1 + i*512*128, eg);
        // ff2 (HMMA)
        EAddBias e2; e2.out = x2; e2.bias = ff_b2 + i*128; e2.ld = 128;
        k_tgemm<<<dim3(1,128),256>>>(ff, 512, wt_ff2 + i*128*512, e2);
    }
    k_layernorm<float><<<16384,128>>>(x1, x2, fin, lnf_g, lnf_b, 0);
    k_pool<<<32,128>>>(fin, out);
}

// round 12
// speedup vs baseline: 2.3583x; 1.9983x over previous
#include <cuda_runtime.h>
#include <cuda_bf16.h>
#include <math.h>
#include <stdint.h>

// B=8 S=512 FDIM=512 SUB=4 DIM=128 HEADS=8 DH=64 INNER=512
// T=2176 (2048+128 mem), NB=34, N_HASHES=4, BUCKET=64, C=136, 4T=8704

__device__ float g_x1 [8*2048*128];
__device__ float g_x2 [8*2048*128];
__device__ float g_fin[8*2048*128];
__device__ float g_aq [8*2176*128];              // fp32 qkv GEMM input (feeds buckets!)
__device__ __nv_bfloat16 g_ain[8*2048*128];      // bf16 ff1 input
__device__ __nv_bfloat16 g_am [8*2048*512];      // bf16 merged attention output
__device__ __nv_bfloat16 g_ff [8*2048*512];      // bf16 gelu output
__device__ float g_qk [8*8*2176*64];
__device__ float g_v  [8*8*2176*64];
__device__ int   g_bkt [48*8704];
__device__ int   g_st  [48*8704];
__device__ int   g_undo[48*8704];
__device__ float g_so  [48*8704*64];
__device__ float g_slog[48*8704];
__device__ __nv_bfloat16 g_wt_out[2][128*512];   // w_out^T  [n=128][k=512]
__device__ __nv_bfloat16 g_wt_ff1[2][512*128];   // ff_w1^T  [n=512][k=128]
__device__ __nv_bfloat16 g_wt_ff2[2][128*512];   // ff_w2^T  [n=128][k=512]

__device__ __forceinline__ uint32_t smem_u32(const void* p){
    uint32_t a;
    asm("{ .reg .u64 t; cvta.to.shared.u64 t, %1; cvt.u32.u64 %0, t; }" : "=r"(a) : "l"(p));
    return a;
}
__device__ __forceinline__ void ldm4(uint32_t& r0, uint32_t& r1, uint32_t& r2, uint32_t& r3,
                                     uint32_t addr){
    asm volatile("ldmatrix.sync.aligned.m8n8.x4.shared.b16 {%0,%1,%2,%3}, [%4];"
        : "=r"(r0),"=r"(r1),"=r"(r2),"=r"(r3) : "r"(addr));
}
__device__ __forceinline__ void ldm4t(uint32_t& r0, uint32_t& r1, uint32_t& r2, uint32_t& r3,
                                      uint32_t addr){
    asm volatile("ldmatrix.sync.aligned.m8n8.x4.trans.shared.b16 {%0,%1,%2,%3}, [%4];"
        : "=r"(r0),"=r"(r1),"=r"(r2),"=r"(r3) : "r"(addr));
}
__device__ __forceinline__ void mma16816(float* c, const uint32_t* a, const uint32_t* b){
    asm volatile("mma.sync.aligned.m16n8k16.row.col.f32.bf16.bf16.f32 "
        "{%0,%1,%2,%3}, {%4,%5,%6,%7}, {%8,%9}, {%0,%1,%2,%3};"
        : "+f"(c[0]),"+f"(c[1]),"+f"(c[2]),"+f"(c[3])
        : "r"(a[0]),"r"(a[1]),"r"(a[2]),"r"(a[3]), "r"(b[0]),"r"(b[1]));
}
__device__ __forceinline__ uint4 f8_to_bf8(float4 a, float4 b){
    __nv_bfloat162 h0 = __floats2bfloat162_rn(a.x, a.y);
    __nv_bfloat162 h1 = __floats2bfloat162_rn(a.z, a.w);
    __nv_bfloat162 h2 = __floats2bfloat162_rn(b.x, b.y);
    __nv_bfloat162 h3 = __floats2bfloat162_rn(b.z, b.w);
    uint4 r;
    r.x = *(uint32_t*)&h0; r.y = *(uint32_t*)&h1;
    r.z = *(uint32_t*)&h2; r.w = *(uint32_t*)&h3;
    return r;
}

// ---- weight convert+transpose: in fp32 [K][N] -> out bf16 [N][K] ----
__global__ void __launch_bounds__(256) k_wcvt(const float* __restrict__ in,
                                              __nv_bfloat16* __restrict__ out,
                                              int K, int N){
    int idx = blockIdx.x*256 + threadIdx.x;
    int n = idx / K, k = idx - n*K;
    out[idx] = __float2bfloat16(in[k*N + n]);
}

// ====== HMMA GEMM: C[M,N] = A[M,K](bf16) * BT[N,K]^T, fp32 epilogue ======
struct EAddBias {
    float* out; const float* bias; int ld;
    __device__ __forceinline__ void operator()(int m, int n, float v) const {
        out[m*ld + n] += v + bias[n];
    }
};
struct EGelu {
    __nv_bfloat16* out; const float* bias;
    __device__ __forceinline__ void operator()(int m, int n, float v) const {
        float h = v + bias[n];
        out[m*512 + n] = __float2bfloat16(0.5f*h*(1.0f + erff(h*0.7071067811865475f)));
    }
};

template<class EP>
__global__ void __launch_bounds__(256) k_tgemm(const __nv_bfloat16* __restrict__ A, int K,
                                               const __nv_bfloat16* __restrict__ BT,
                                               EP ep){
    __shared__ __nv_bfloat16 As[128][72];
    __shared__ __nv_bfloat16 Bs[128][72];
    int tid = threadIdx.x, wid = tid >> 5, lane = tid & 31;
    int wm = wid >> 1, wn = wid & 1;
    int bm = blockIdx.y*128, bn = blockIdx.x*128;
    float acc[2][8][4] = {};
    int nc = K >> 6;
    for (int kc = 0; kc < nc; kc++){
        for (int p = tid; p < 1024; p += 256){
            int row = p >> 3, q = p & 7;
            *(uint4*)&As[row][q*8] = *(const uint4*)(A  + (size_t)(bm+row)*K + kc*64 + q*8);
            *(uint4*)&Bs[row][q*8] = *(const uint4*)(BT + (size_t)(bn+row)*K + kc*64 + q*8);
        }
        __syncthreads();
#pragma unroll
        for (int s = 0; s < 4; s++){
            uint32_t af[2][4];
#pragma unroll
            for (int mt = 0; mt < 2; mt++){
                uint32_t addr = smem_u32(&As[wm*32 + mt*16 + (lane & 15)][s*16 + (lane >> 4)*8]);
                ldm4(af[mt][0], af[mt][1], af[mt][2], af[mt][3], addr);
            }
            uint32_t bf[8][2];
#pragma unroll
            for (int nt16 = 0; nt16 < 4; nt16++){
                int mi = lane >> 3;
                uint32_t addr = smem_u32(&Bs[wn*64 + nt16*16 + (mi >> 1)*8 + (lane & 7)][s*16 + (mi & 1)*8]);
                uint32_t r0,r1,r2,r3;
                ldm4(r0,r1,r2,r3, addr);
                bf[nt16*2][0]   = r0; bf[nt16*2][1]   = r1;
                bf[nt16*2+1][0] = r2; bf[nt16*2+1][1] = r3;
            }
#pragma unroll
            for (int mt = 0; mt < 2; mt++)
#pragma unroll
                for (int nt = 0; nt < 8; nt++)
                    mma16816(acc[mt][nt], af[mt], bf[nt]);
        }
        __syncthreads();
    }
#pragma unroll
    for (int mt = 0; mt < 2; mt++){
#pragma unroll
        for (int nt = 0; nt < 8; nt++){
            int m = bm + wm*32 + mt*16 + (lane >> 2);
            int n = bn + wn*64 + nt*8 + (lane & 3)*2;
            ep(m,   n,   acc[mt][nt][0]);
            ep(m,   n+1, acc[mt][nt][1]);
            ep(m+8, n,   acc[mt][nt][2]);
            ep(m+8, n+1, acc[mt][nt][3]);
        }
    }
}

// ================= rest of pipeline =================
__global__ void __launch_bounds__(256) k_embed(const float* __restrict__ feat){
    int idx = blockIdx.x*256 + threadIdx.x;
    int b = idx >> 18, r = idx & 262143;
    int t = r >> 7, d = r & 127;
    int s = t >> 2, f = ((t & 3) << 7) + d;
    float inv = expf(-(2.0f*(float)f/512.0f)*9.210340371976184f);
    float ang = (float)s * inv;
    float pe = (f & 1) ? cosf(ang) : sinf(ang);
    float v = feat[(b*512 + s)*512 + f] + pe;
    g_x1[idx] = v; g_x2[idx] = v;
}

template<typename OutT>
__global__ void __launch_bounds__(128) k_layernorm(const float* __restrict__ in1,
                                                   const float* __restrict__ in2,
                                                   OutT* __restrict__ outp,
                                                   const float* __restrict__ gam,
                                                   const float* __restrict__ bet,
                                                   int pack){
    int row = blockIdx.x, d = threadIdx.x;
    float x = in1[row*128 + d];
    if (in2) x = 0.5f*(x + in2[row*128 + d]);
    __shared__ float sh[4];
    float s = x;
#pragma unroll
    for (int o=16;o>0;o>>=1) s += __shfl_xor_sync(0xffffffffu, s, o);
    if ((d & 31) == 0) sh[d>>5] = s;
    __syncthreads();
    float mean = (sh[0]+sh[1]+sh[2]+sh[3]) * (1.0f/128.0f);
    float c = x - mean;
    __syncthreads();
    float v = c*c;
#pragma unroll
    for (int o=16;o>0;o>>=1) v += __shfl_xor_sync(0xffffffffu, v, o);
    if ((d & 31) == 0) sh[d>>5] = v;
    __syncthreads();
    float var = (sh[0]+sh[1]+sh[2]+sh[3]) * (1.0f/128.0f);
    int orow = pack ? row + (row>>11)*128 : row;
    outp[orow*128 + d] = (OutT)(c * rsqrtf(var + 1e-5f) * gam[d] + bet[d]);
}

__global__ void __launch_bounds__(256) k_memfill(const float* __restrict__ mem){
    int idx = blockIdx.x*256 + threadIdx.x;
    int b = idx >> 12, r = idx & 4095;
    float4 v = ((const float4*)mem)[r];
    ((float4*)(g_aq + (b*2176 + 2048)*128))[r] = v;
}

// fp32 GEMM (qkv only — feeds LSH argmax, must stay fp32)
struct EQKV {
    float* out;
    __device__ __forceinline__ void operator()(int m, int n, float v) const {
        int b = m / 2176, t = m - b*2176;
        out[(((b<<3) + (n>>6))*2176 + t)*64 + (n & 63)] = v;
    }
};
template<class EP>
__global__ void __launch_bounds__(256) k_gemm(const float* __restrict__ A, int K,
                                              const float* __restrict__ Bm, int N,
                                              EP ep){
    __shared__ float As[2][16][132];
    __shared__ float Bs[2][16][132];
    int bm = blockIdx.y*128, bn = blockIdx.x*128;
    int tid = threadIdx.x, tx = tid & 15, ty = tid >> 4;
    int arow = tid >> 1, aq = tid & 1;
    int bkk = tid >> 4, bv = tid & 15;
    float acc[8][8] = {};
    const float* Arow = A + (bm+arow)*K;
    {
        float4 a0 = *(const float4*)(Arow + aq*4);
        float4 a1 = *(const float4*)(Arow + (aq+2)*4);
        float4 b0 = *(const float4*)(Bm + bkk*N + bn + bv*4);
        float4 b1 = *(const float4*)(Bm + bkk*N + bn + bv*4 + 64);
        As[0][aq*4+0][arow] = a0.x; As[0][aq*4+1][arow] = a0.y;
        As[0][aq*4+2][arow] = a0.z; As[0][aq*4+3][arow] = a0.w;
        As[0][aq*4+8][arow] = a1.x; As[0][aq*4+9][arow] = a1.y;
        As[0][aq*4+10][arow] = a1.z; As[0][aq*4+11][arow] = a1.w;
        *(float4*)&Bs[0][bkk][bv*4]      = b0;
        *(float4*)&Bs[0][bkk][bv*4 + 64] = b1;
    }
    __syncthreads();
    int nt = K >> 4;
    for (int t = 0; t < nt; t++){
        int cur = t & 1, nxt = cur ^ 1;
        float4 na0, na1, nb0, nb1;
        if (t+1 < nt){
            int k0 = (t+1) << 4;
            na0 = *(const float4*)(Arow + k0 + aq*4);
            na1 = *(const float4*)(Arow + k0 + (aq+2)*4);
            nb0 = *(const float4*)(Bm + (k0+bkk)*N + bn + bv*4);
            nb1 = *(const float4*)(Bm + (k0+bkk)*N + bn + bv*4 + 64);
        }
#pragma unroll
        for (int kk=0;kk<16;kk++){
            float4 a0 = *(float4*)&As[cur][kk][ty*8];
            float4 a1 = *(float4*)&As[cur][kk][ty*8+4];
            float4 b0 = *(float4*)&Bs[cur][kk][tx*8];
            float4 b1 = *(float4*)&Bs[cur][kk][tx*8+4];
            float av[8] = {a0.x,a0.y,a0.z,a0.w,a1.x,a1.y,a1.z,a1.w};
            float bv2[8] = {b0.x,b0.y,b0.z,b0.w,b1.x,b1.y,b1.z,b1.w};
#pragma unroll
            for (int i=0;i<8;i++)
#pragma unroll
                for (int j=0;j<8;j++) acc[i][j] = fmaf(av[i], bv2[j], acc[i][j]);
        }
        if (t+1 < nt){
            As[nxt][aq*4+0][arow] = na0.x; As[nxt][aq*4+1][arow] = na0.y;
            As[nxt][aq*4+2][arow] = na0.z; As[nxt][aq*4+3][arow] = na0.w;
            As[nxt][aq*4+8][arow] = na1.x; As[nxt][aq*4+9][arow] = na1.y;
            As[nxt][aq*4+10][arow] = na1.z; As[nxt][aq*4+11][arow] = na1.w;
            *(float4*)&Bs[nxt][bkk][bv*4]      = nb0;
            *(float4*)&Bs[nxt][bkk][bv*4 + 64] = nb1;
            __syncthreads();
        }
    }
#pragma unroll
    for (int i=0;i<8;i++)
#pragma unroll
        for (int j=0;j<8;j++) ep(bm + ty*8 + i, bn + tx*8 + j, acc[i][j]);
}

__global__ void __launch_bounds__(128) k_buckets(const float* __restrict__ rot){
    __shared__ float srot[4352];
    int tid = threadIdx.x;
    for (int i = tid; i < 4352; i += 128) srot[i] = rot[i];
    __syncthreads();
    int bh = blockIdx.x, t = blockIdx.y*128 + tid;
    int b = bh / 6, head = 2 + bh % 6;
    const float* qp = g_qk + (((b<<3) + head)*2176 + t)*64;
    float rv[68];
#pragma unroll
    for (int u=0;u<68;u++) rv[u] = 0.0f;
    for (int f=0; f<64; f++){
        float qf = qp[f];
        const float* rp = &srot[f*68];
#pragma unroll
        for (int u=0;u<68;u++) rv[u] = fmaf(qf, rp[u], rv[u]);
    }
#pragma unroll
    for (int h=0; h<4; h++){
        float best = rv[h*17]; int bi = 0;
#pragma unroll
        for (int i=1;i<17;i++){ float v = rv[h*17+i]; if (v > best){ best = v; bi = i; } }
#pragma unroll
        for (int i=0;i<17;i++){ float v = -rv[h*17+i]; if (v > best){ best = v; bi = 17+i; } }
        g_bkt[bh*8704 + h*2176 + t] = bi + h*34;
    }
}

__global__ void __launch_bounds__(64) k_sort(){
    __shared__ int hist[64][136];
    __shared__ int base[136];
    int bh = blockIdx.x, t = threadIdx.x;
    int* hrow = hist[t];
    for (int i=0;i<136;i++) hrow[i] = 0;
    const int* bk = g_bkt + bh*8704;
    int i0 = t*136;
    for (int i=0;i<136;i++) hrow[bk[i0+i]]++;
    __syncthreads();
    for (int c = t; c < 136; c += 64){
        int run = 0;
        for (int tt=0; tt<64; tt++){ int v = hist[tt][c]; hist[tt][c] = run; run += v; }
        base[c] = run;
    }
    __syncthreads();
    if (t == 0){
        int run = 0;
        for (int c=0;c<136;c++){ int v = base[c]; base[c] = run; run += v; }
    }
    __syncthreads();
    for (int i=0;i<136;i++){
        int idx = i0 + i, bb = bk[idx];
        int pos = base[bb] + hrow[bb]; hrow[bb]++;
        g_st  [bh*8704 + pos] = idx % 2176;
        g_undo[bh*8704 + idx] = pos;
    }
}

// ---- LSH chunk attention: HMMA dots + PV ----
__global__ void __launch_bounds__(256) k_lsh_attn(){
    extern __shared__ char smc[];
    __nv_bfloat16* skb = (__nv_bfloat16*)smc;              // [128][72] q/k rows
    __nv_bfloat16* svb = (__nv_bfloat16*)(smc + 18432);    // [128][72] v rows
    float* sd          = (float*)(smc + 36864);            // [64][128] logits
    __nv_bfloat16* sp  = (__nv_bfloat16*)(smc + 69632);    // [64][136] probs bf16
    float* scale       = (float*)(smc + 87040);            // [128]
    int*   skt         = (int*)(smc + 87552);              // [128]
    int bh = blockIdx.x, c = blockIdx.y, tid = threadIdx.x;
    int wid = tid >> 5, lane = tid & 31;
    int base  = bh*8704 + c*64;
    int pbase = bh*8704 + ((c + 135) % 136)*64;
    int b = bh / 6, head = 2 + bh % 6;
    int bhh = (b<<3) + head;
    for (int p = tid; p < 1024; p += 256){
        int row = p >> 3, c8 = p & 7;
        int src = (row < 64) ? g_st[base + row] : g_st[pbase + row - 64];
        const float4* qp = (const float4*)(g_qk + (bhh*2176 + src)*64 + c8*8);
        const float4* vp = (const float4*)(g_v  + (bhh*2176 + src)*64 + c8*8);
        *(uint4*)&skb[row*72 + c8*8] = f8_to_bf8(qp[0], qp[1]);
        *(uint4*)&svb[row*72 + c8*8] = f8_to_bf8(vp[0], vp[1]);
    }
    if (tid < 128)
        skt[tid] = (tid < 64) ? g_st[base + tid] : g_st[pbase + tid - 64];
    __syncthreads();
    if (tid < 128){
        float s = 0.f;
        const uint32_t* rp = (const uint32_t*)(skb + tid*72);
#pragma unroll
        for (int i = 0; i < 32; i++){
            float2 f = __bfloat1622float2(*(const __nv_bfloat162*)&rp[i]);
            s += f.x*f.x + f.y*f.y;
        }
        scale[tid] = 1.0f / fmaxf(sqrtf(s), 1e-12f);
    }
    __syncthreads();
    int wm = wid >> 1, wn = wid & 1;     // warp tile dots: rows wm*16, cols wn*64
    {
        float dacc[8][4] = {};
#pragma unroll
        for (int s = 0; s < 4; s++){
            uint32_t af[4];
            ldm4(af[0],af[1],af[2],af[3],
                 smem_u32(&skb[(wm*16 + (lane & 15))*72 + s*16 + (lane >> 4)*8]));
            uint32_t bf[8][2];
#pragma unroll
            for (int nt16 = 0; nt16 < 4; nt16++){
                int mi = lane >> 3;
                uint32_t r0,r1,r2,r3;
                ldm4(r0,r1,r2,r3,
                     smem_u32(&skb[(wn*64 + nt16*16 + (mi >> 1)*8 + (lane & 7))*72 + s*16 + (mi & 1)*8]));
                bf[nt16*2][0]   = r0; bf[nt16*2][1]   = r1;
                bf[nt16*2+1][0] = r2; bf[nt16*2+1][1] = r3;
            }
#pragma unroll
            for (int nt = 0; nt < 8; nt++)
                mma16816(dacc[nt], af, bf[nt]);
        }
#pragma unroll
        for (int nt = 0; nt < 8; nt++){
            int row = wm*16 + (lane >> 2);
            int col = wn*64 + nt*8 + (lane & 3)*2;
#pragma unroll
            for (int e = 0; e < 4; e++){
                int r = row + (e >> 1)*8, cc = col + (e & 1);
                int tq = skt[r], tk = skt[cc];
                float v = dacc[nt][e]*scale[cc]*0.125f;
                if (tq < tk)       v = -1e9f;
                else if (tq == tk) v = -5e4f;
                sd[r*128 + cc] = v;
            }
        }
    }
    __syncthreads();
    {   // softmax + logsumexp per row; write probs bf16 to sp
        int warp = wid, ln = lane;
        for (int rr=0; rr<8; rr++){
            int row = warp*8 + rr;
            float d0[4];
#pragma unroll
            for (int j=0;j<4;j++) d0[j] = sd[row*128 + ln + 32*j];
            float m = fmaxf(fmaxf(d0[0],d0[1]), fmaxf(d0[2],d0[3]));
#pragma unroll
            for (int o=16;o>0;o>>=1) m = fmaxf(m, __shfl_xor_sync(0xffffffffu, m, o));
            float p[4], s = 0.f;
#pragma unroll
            for (int j=0;j<4;j++){ p[j] = __expf(d0[j]-m); s += p[j]; }
#pragma unroll
            for (int o=16;o>0;o>>=1) s += __shfl_xor_sync(0xffffffffu, s, o);
            float inv = 1.0f/s;
#pragma unroll
            for (int j=0;j<4;j++) sp[row*136 + ln + 32*j] = __float2bfloat16(p[j]*inv);
            if (ln == 0) g_slog[base + row] = m + __logf(s);
        }
    }
    __syncthreads();
    {   // PV: C[64][64] = P[64][128] @ V[128][64]; warp tile rows wm*16, cols wn*32
        float pacc[4][4] = {};
#pragma unroll
        for (int s = 0; s < 8; s++){
            uint32_t af[4];
            ldm4(af[0],af[1],af[2],af[3],
                 smem_u32(&sp[(wm*16 + (lane & 15))*136 + s*16 + (lane >> 4)*8]));
            uint32_t bf[4][2];
#pragma unroll
            for (int nt16 = 0; nt16 < 2; nt16++){
                int mi = lane >> 3;
                uint32_t r0,r1,r2,r3;
                // trans-B from row-major V[j][d]: tile rows = k (j), cols = n (d)
                ldm4t(r0,r1,r2,r3,
                      smem_u32(&svb[(s*16 + (mi & 1)*8 + (lane & 7))*72 + wn*32 + nt16*16 + (mi >> 1)*8]));
                bf[nt16*2][0]   = r0; bf[nt16*2][1]   = r1;
                bf[nt16*2+1][0] = r2; bf[nt16*2+1][1] = r3;
            }
#pragma unroll
            for (int nt = 0; nt < 4; nt++)
                mma16816(pacc[nt], af, bf[nt]);
        }
#pragma unroll
        for (int nt = 0; nt < 4; nt++){
            int row = wm*16 + (lane >> 2);
            int col = wn*32 + nt*8 + (lane & 3)*2;
            g_so[(base + row)*64 + col]     = pacc[nt][0];
            g_so[(base + row)*64 + col + 1] = pacc[nt][1];
            g_so[(base + row + 8)*64 + col]     = pacc[nt][2];
            g_so[(base + row + 8)*64 + col + 1] = pacc[nt][3];
        }
    }
}

__global__ void __launch_bounds__(256) k_unsort(){
    int bh = blockIdx.y, tid = threadIdx.x;
    int g = tid >> 6, d = tid & 63;
    int t = blockIdx.x*4 + g;
    __shared__ int pos[4][4]; __shared__ float w[4][4];
    if (d < 4){
        int p = g_undo[bh*8704 + d*2176 + t];
        pos[g][d] = p; w[g][d] = g_slog[bh*8704 + p];
    }
    __syncthreads();
    if (d == 0){
        float m = fmaxf(fmaxf(w[g][0],w[g][1]), fmaxf(w[g][2],w[g][3]));
        float s = 0.f;
        for (int h=0;h<4;h++){ w[g][h] = __expf(w[g][h]-m); s += w[g][h]; }
        float inv = 1.0f/s;
        for (int h=0;h<4;h++) w[g][h] *= inv;
    }
    __syncthreads();
    float o = 0.f;
    for (int h=0;h<4;h++) o += w[g][h]*g_so[(bh*8704 + pos[g][h])*64 + d];
    int b = bh / 6, head = 2 + bh % 6;
    g_am[(b*2048 + t)*512 + head*64 + d] = __float2bfloat16(o);
}

__global__ void __launch_bounds__(256) k_local_attn(){
    extern __shared__ float sm[];
    float* skv   = sm;
    float* sv    = sm + 17408;
    float* sd    = sm + 34816;
    float* scale = sm + 51200;
    int bh = blockIdx.x, b = bh >> 1, head = bh & 1;
    int win = blockIdx.y, half = blockIdx.z;
    int tid = threadIdx.x;
    const float* qbase = g_qk + (((b<<3) + head)*2176)*64;
    const float* vbase = g_v  + (((b<<3) + head)*2176)*64;
    int q0 = win*128 + half*64;
    int qrow = 128 + half*64;
    for (int p = tid; p < 256*16; p += 256){
        int row = p >> 4, v4 = p & 15;
        float4 kv, vv;
        if (row < 128 && win == 0){
            kv = make_float4(0,0,0,0); vv = kv;
        } else {
            int t = (row < 128) ? (win-1)*128 + row : win*128 + row - 128;
            kv = ((const float4*)(qbase + t*64))[v4];
            vv = ((const float4*)(vbase + t*64))[v4];
        }
        *(float4*)&skv[row*68 + v4*4] = kv;
        *(float4*)&sv [row*68 + v4*4] = vv;
    }
    __syncthreads();
    {
        float s = 0.f;
#pragma unroll
        for (int d=0;d<64;d+=4){
            float4 v = *(float4*)&skv[tid*68 + d];
            s += v.x*v.x + v.y*v.y + v.z*v.z + v.w*v.w;
        }
        scale[tid] = 1.0f / fmaxf(sqrtf(s), 1e-12f);
    }
    __syncthreads();
    int ty = tid >> 4, tx = tid & 15;
    int i0 = ty*4;
    for (int jt=0; jt<2; jt++){
        int jb = tx*8 + jt*128;
        float acc[4][8] = {};
        for (int d=0; d<64; d+=4){
            float4 a[4], bb[8];
#pragma unroll
            for (int i=0;i<4;i++) a[i]  = *(float4*)&skv[(qrow+i0+i)*68 + d];
#pragma unroll
            for (int j=0;j<8;j++) bb[j] = *(float4*)&skv[(jb+j)*68 + d];
#pragma unroll
            for (int i=0;i<4;i++)
#pragma unroll
                for (int j=0;j<8;j++){
                    acc[i][j] = fmaf(a[i].x, bb[j].x, acc[i][j]);
                    acc[i][j] = fmaf(a[i].y, bb[j].y, acc[i][j]);
                    acc[i][j] = fmaf(a[i].z, bb[j].z, acc[i][j]);
                    acc[i][j] = fmaf(a[i].w, bb[j].w, acc[i][j]);
                }
        }
#pragma unroll
        for (int i=0;i<4;i++){
            int tq = q0 + i0 + i;
#pragma unroll
            for (int j=0;j<8;j++){
                int jc = jb + j;
                float v = acc[i][j]*scale[jc]*0.125f;
                if (jc < 128){
                    if (win == 0) v = -1e9f;
                    else {
                        int tk = (win-1)*128 + jc;
                        if (tq == tk) v = -5e4f; else if (tq < tk) v = -1e9f;
                    }
                } else {
                    int tk = win*128 + jc - 128;
                    if (tq == tk) v = -5e4f; else if (tq < tk) v = -1e9f;
                }
                sd[(i0+i)*256 + jc] = v;
            }
        }
    }
    __syncthreads();
    {
        int warp = tid >> 5, lane = tid & 31;
        for (int rr=0; rr<8; rr++){
            int row = warp*8 + rr;
            float d0[8];
#pragma unroll
            for (int j=0;j<8;j++) d0[j] = sd[row*256 + lane + 32*j];
            float m = d0[0];
#pragma unroll
            for (int j=1;j<8;j++) m = fmaxf(m, d0[j]);
#pragma unroll
            for (int o=16;o>0;o>>=1) m = fmaxf(m, __shfl_xor_sync(0xffffffffu, m, o));
            float p[8], s = 0.f;
#pragma unroll
            for (int j=0;j<8;j++){ p[j] = __expf(d0[j]-m); s += p[j]; }
#pragma unroll
            for (int o=16;o>0;o>>=1) s += __shfl_xor_sync(0xffffffffu, s, o);
            float inv = 1.0f/s;
#pragma unroll
            for (int j=0;j<8;j++) sd[row*256 + lane + 32*j] = p[j]*inv;
        }
    }
    __syncthreads();
    {
        int d0 = tx*4;
        float acc[4][4] = {};
        for (int j=0; j<256; j+=4){
            float4 p[4], vv[4];
#pragma unroll
            for (int i=0;i<4;i++)    p[i]  = *(float4*)&sd[(i0+i)*256 + j];
#pragma unroll
            for (int j2=0;j2<4;j2++) vv[j2] = *(float4*)&sv[(j+j2)*68 + d0];
#pragma unroll
            for (int i=0;i<4;i++){
                acc[i][0] = fmaf(p[i].x, vv[0].x, acc[i][0]);
                acc[i][0] = fmaf(p[i].y, vv[1].x, acc[i][0]);
                acc[i][0] = fmaf(p[i].z, vv[2].x, acc[i][0]);
                acc[i][0] = fmaf(p[i].w, vv[3].x, acc[i][0]);
                acc[i][1] = fmaf(p[i].x, vv[0].y, acc[i][1]);
                acc[i][1] = fmaf(p[i].y, vv[1].y, acc[i][1]);
                acc[i][1] = fmaf(p[i].z, vv[2].y, acc[i][1]);
                acc[i][1] = fmaf(p[i].w, vv[3].y, acc[i][1]);
                acc[i][2] = fmaf(p[i].x, vv[0].z, acc[i][2]);
                acc[i][2] = fmaf(p[i].y, vv[1].z, acc[i][2]);
                acc[i][2] = fmaf(p[i].z, vv[2].z, acc[i][2]);
                acc[i][2] = fmaf(p[i].w, vv[3].z, acc[i][2]);
                acc[i][3] = fmaf(p[i].x, vv[0].w, acc[i][3]);
                acc[i][3] = fmaf(p[i].y, vv[1].w, acc[i][3]);
                acc[i][3] = fmaf(p[i].z, vv[2].w, acc[i][3]);
                acc[i][3] = fmaf(p[i].w, vv[3].w, acc[i][3]);
            }
        }
#pragma unroll
        for (int i=0;i<4;i++){
            int t = q0 + i0 + i;
            if (t < 2048)
#pragma unroll
                for (int d=0;d<4;d++)
                    g_am[(b*2048 + t)*512 + head*64 + d0 + d] = __float2bfloat16(acc[i][d]);
        }
    }
}

__global__ void __launch_bounds__(128) k_pool(const float* __restrict__ in, float* __restrict__ out){
    int b = blockIdx.x >> 2, sub = blockIdx.x & 3, d = threadIdx.x;
    const float* p = in + (b*2048 + sub)*128 + d;
    float s = 0.f;
    for (int i=0;i<512;i++) s += p[i*512];
    out[b*512 + sub*128 + d] = s * (1.0f/512.0f);
}

extern "C" void kernel_launch(void* const* d_in, const int* in_sizes, int n_in,
                              void* d_out, int out_size){
    const float* features  = (const float*)d_in[0];
    const float* w_qk      = (const float*)d_in[1];
    const float* w_v       = (const float*)d_in[2];
    const float* mem_kv    = (const float*)d_in[3];
    const float* w_out     = (const float*)d_in[4];
    const float* b_out     = (const float*)d_in[5];
    const float* ln1_g     = (const float*)d_in[6];
    const float* ln1_b     = (const float*)d_in[7];
    const float* ff_w1     = (const float*)d_in[8];
    const float* ff_b1     = (const float*)d_in[9];
    const float* ff_w2     = (const float*)d_in[10];
    const float* ff_b2     = (const float*)d_in[11];
    const float* ln2_g     = (const float*)d_in[12];
    const float* ln2_b     = (const float*)d_in[13];
    const float* lnf_g     = (const float*)d_in[14];
    const float* lnf_b     = (const float*)d_in[15];
    const float* rotations = (const float*)d_in[16];
    float* out = (float*)d_out;

    float *x1,*x2,*fin,*aq,*qk,*vv;
    __nv_bfloat16 *ain,*am,*ff,*wt_out,*wt_ff1,*wt_ff2;
    cudaGetSymbolAddress((void**)&x1,  g_x1);
    cudaGetSymbolAddress((void**)&x2,  g_x2);
    cudaGetSymbolAddress((void**)&fin, g_fin);
    cudaGetSymbolAddress((void**)&aq,  g_aq);
    cudaGetSymbolAddress((void**)&qk,  g_qk);
    cudaGetSymbolAddress((void**)&vv,  g_v);
    cudaGetSymbolAddress((void**)&ain, g_ain);
    cudaGetSymbolAddress((void**)&am,  g_am);
    cudaGetSymbolAddress((void**)&ff,  g_ff);
    cudaGetSymbolAddress((void**)&wt_out, g_wt_out);
    cudaGetSymbolAddress((void**)&wt_ff1, g_wt_ff1);
    cudaGetSymbolAddress((void**)&wt_ff2, g_wt_ff2);

    const int LSH_SMEM = 88064;
    const int LOC_SMEM = 205824;
    cudaFuncSetAttribute(k_lsh_attn,   cudaFuncAttributeMaxDynamicSharedMemorySize, LSH_SMEM);
    cudaFuncSetAttribute(k_local_attn, cudaFuncAttributeMaxDynamicSharedMemorySize, LOC_SMEM);

    for (int i = 0; i < 2; i++){
        k_wcvt<<<(128*512)/256,256>>>(w_out + i*512*128, wt_out + i*128*512, 512, 128);
        k_wcvt<<<(512*128)/256,256>>>(ff_w1 + i*128*512, wt_ff1 + i*512*128, 128, 512);
        k_wcvt<<<(128*512)/256,256>>>(ff_w2 + i*512*128, wt_ff2 + i*128*512, 512, 128);
    }

    k_embed<<<8192, 256>>>(features);

    for (int i = 0; i < 2; i++){
        k_layernorm<float><<<16384,128>>>(x2, (const float*)0, aq, ln1_g + i*128, ln1_b + i*128, 1);
        k_memfill<<<128,256>>>(mem_kv + i*128*128);
        EQKV eq; eq.out = qk;
        EQKV ev; ev.out = vv;
        k_gemm<<<dim3(4,136),256>>>(aq, 128, w_qk + i*128*512, 512, eq);
        k_gemm<<<dim3(4,136),256>>>(aq, 128, w_v  + i*128*512, 512, ev);
        k_local_attn<<<dim3(16,17,2),256,LOC_SMEM>>>();
        k_buckets<<<dim3(48,17),128>>>(rotations + i*64*4*17);
        k_sort<<<48,64>>>();
        k_lsh_attn<<<dim3(48,136),256,LSH_SMEM>>>();
        k_unsort<<<dim3(512,48),256>>>();
        EAddBias e1; e1.out = x1; e1.bias = b_out + i*128; e1.ld = 128;
        k_tgemm<<<dim3(1,128),256>>>(am, 512, wt_out + i*128*512, e1);
        k_layernorm<__nv_bfloat16><<<16384,128>>>(x1, (const float*)0, ain, ln2_g + i*128, ln2_b + i*128, 0);
        EGelu eg; eg.out = ff; eg.bias = ff_b1 + i*512;
        k_tgemm<<<dim3(4,128),256>>>(ain, 128, wt_ff1 + i*512*128, eg);
        EAddBias e2; e2.out = x2; e2.bias = ff_b2 + i*128; e2.ld = 128;
        k_tgemm<<<dim3(1,128),256>>>(ff, 512, wt_ff2 + i*128*512, e2);
    }
    k_layernorm<float><<<16384,128>>>(x1, x2, fin, lnf_g, lnf_b, 0);
    k_pool<<<32,128>>>(fin, out);
}

// round 13
// speedup vs baseline: 2.9005x; 1.2299x over previous
#include <cuda_runtime.h>
#include <cuda_bf16.h>
#include <math.h>
#include <stdint.h>

// B=8 S=512 FDIM=512 SUB=4 DIM=128 HEADS=8 DH=64 INNER=512
// T=2176 (2048+128 mem), NB=34, N_HASHES=4, BUCKET=64, C=136, 4T=8704

__device__ float g_x1 [8*2048*128];
__device__ float g_x2 [8*2048*128];
__device__ float g_fin[8*2048*128];
__device__ float g_aq [8*2176*128];              // fp32 qkv GEMM input (feeds buckets!)
__device__ __nv_bfloat16 g_ain[8*2048*128];      // bf16 ff1 input
__device__ __nv_bfloat16 g_am [8*2048*512];      // bf16 merged attention output
__device__ __nv_bfloat16 g_ff [8*2048*512];      // bf16 gelu output
__device__ float g_qk [8*8*2176*64];
__device__ float g_v  [8*8*2176*64];
__device__ int   g_bkt [48*8704];
__device__ int   g_st  [48*8704];
__device__ int   g_undo[48*8704];
__device__ float g_so  [48*8704*64];
__device__ float g_slog[48*8704];
__device__ __nv_bfloat16 g_wt_out[2][128*512];   // w_out^T  [n=128][k=512]
__device__ __nv_bfloat16 g_wt_ff1[2][512*128];   // ff_w1^T  [n=512][k=128]
__device__ __nv_bfloat16 g_wt_ff2[2][128*512];   // ff_w2^T  [n=128][k=512]

__device__ __forceinline__ uint32_t smem_u32(const void* p){
    uint32_t a;
    asm("{ .reg .u64 t; cvta.to.shared.u64 t, %1; cvt.u32.u64 %0, t; }" : "=r"(a) : "l"(p));
    return a;
}
__device__ __forceinline__ void ldm4(uint32_t& r0, uint32_t& r1, uint32_t& r2, uint32_t& r3,
                                     uint32_t addr){
    asm volatile("ldmatrix.sync.aligned.m8n8.x4.shared.b16 {%0,%1,%2,%3}, [%4];"
        : "=r"(r0),"=r"(r1),"=r"(r2),"=r"(r3) : "r"(addr));
}
__device__ __forceinline__ void ldm4t(uint32_t& r0, uint32_t& r1, uint32_t& r2, uint32_t& r3,
                                      uint32_t addr){
    asm volatile("ldmatrix.sync.aligned.m8n8.x4.trans.shared.b16 {%0,%1,%2,%3}, [%4];"
        : "=r"(r0),"=r"(r1),"=r"(r2),"=r"(r3) : "r"(addr));
}
__device__ __forceinline__ void mma16816(float* c, const uint32_t* a, const uint32_t* b){
    asm volatile("mma.sync.aligned.m16n8k16.row.col.f32.bf16.bf16.f32 "
        "{%0,%1,%2,%3}, {%4,%5,%6,%7}, {%8,%9}, {%0,%1,%2,%3};"
        : "+f"(c[0]),"+f"(c[1]),"+f"(c[2]),"+f"(c[3])
        : "r"(a[0]),"r"(a[1]),"r"(a[2]),"r"(a[3]), "r"(b[0]),"r"(b[1]));
}
__device__ __forceinline__ uint4 f8_to_bf8(float4 a, float4 b){
    __nv_bfloat162 h0 = __floats2bfloat162_rn(a.x, a.y);
    __nv_bfloat162 h1 = __floats2bfloat162_rn(a.z, a.w);
    __nv_bfloat162 h2 = __floats2bfloat162_rn(b.x, b.y);
    __nv_bfloat162 h3 = __floats2bfloat162_rn(b.z, b.w);
    uint4 r;
    r.x = *(uint32_t*)&h0; r.y = *(uint32_t*)&h1;
    r.z = *(uint32_t*)&h2; r.w = *(uint32_t*)&h3;
    return r;
}

// ---- weight convert+transpose: in fp32 [K][N] -> out bf16 [N][K] ----
__global__ void __launch_bounds__(256) k_wcvt(const float* __restrict__ in,
                                              __nv_bfloat16* __restrict__ out,
                                              int K, int N){
    int idx = blockIdx.x*256 + threadIdx.x;
    int n = idx / K, k = idx - n*K;
    out[idx] = __float2bfloat16(in[k*N + n]);
}

// ====== HMMA GEMM: C[M,N] = A[M,K](bf16) * BT[N,K]^T, fp32 epilogue ======
struct EAddBias {
    float* out; const float* bias; int ld;
    __device__ __forceinline__ void operator()(int m, int n, float v) const {
        out[m*ld + n] += v + bias[n];
    }
};
struct EGelu {
    __nv_bfloat16* out; const float* bias;
    __device__ __forceinline__ void operator()(int m, int n, float v) const {
        float h = v + bias[n];
        out[m*512 + n] = __float2bfloat16(0.5f*h*(1.0f + erff(h*0.7071067811865475f)));
    }
};

template<class EP>
__global__ void __launch_bounds__(256) k_tgemm(const __nv_bfloat16* __restrict__ A, int K,
                                               const __nv_bfloat16* __restrict__ BT,
                                               EP ep){
    __shared__ __nv_bfloat16 As[128][72];
    __shared__ __nv_bfloat16 Bs[128][72];
    int tid = threadIdx.x, wid = tid >> 5, lane = tid & 31;
    int wm = wid >> 1, wn = wid & 1;
    int bm = blockIdx.y*128, bn = blockIdx.x*128;
    float acc[2][8][4] = {};
    int nc = K >> 6;
    for (int kc = 0; kc < nc; kc++){
        for (int p = tid; p < 1024; p += 256){
            int row = p >> 3, q = p & 7;
            *(uint4*)&As[row][q*8] = *(const uint4*)(A  + (size_t)(bm+row)*K + kc*64 + q*8);
            *(uint4*)&Bs[row][q*8] = *(const uint4*)(BT + (size_t)(bn+row)*K + kc*64 + q*8);
        }
        __syncthreads();
#pragma unroll
        for (int s = 0; s < 4; s++){
            uint32_t af[2][4];
#pragma unroll
            for (int mt = 0; mt < 2; mt++){
                uint32_t addr = smem_u32(&As[wm*32 + mt*16 + (lane & 15)][s*16 + (lane >> 4)*8]);
                ldm4(af[mt][0], af[mt][1], af[mt][2], af[mt][3], addr);
            }
            uint32_t bf[8][2];
#pragma unroll
            for (int nt16 = 0; nt16 < 4; nt16++){
                int mi = lane >> 3;
                uint32_t addr = smem_u32(&Bs[wn*64 + nt16*16 + (mi >> 1)*8 + (lane & 7)][s*16 + (mi & 1)*8]);
                uint32_t r0,r1,r2,r3;
                ldm4(r0,r1,r2,r3, addr);
                bf[nt16*2][0]   = r0; bf[nt16*2][1]   = r1;
                bf[nt16*2+1][0] = r2; bf[nt16*2+1][1] = r3;
            }
#pragma unroll
            for (int mt = 0; mt < 2; mt++)
#pragma unroll
                for (int nt = 0; nt < 8; nt++)
                    mma16816(acc[mt][nt], af[mt], bf[nt]);
        }
        __syncthreads();
    }
#pragma unroll
    for (int mt = 0; mt < 2; mt++){
#pragma unroll
        for (int nt = 0; nt < 8; nt++){
            int m = bm + wm*32 + mt*16 + (lane >> 2);
            int n = bn + wn*64 + nt*8 + (lane & 3)*2;
            ep(m,   n,   acc[mt][nt][0]);
            ep(m,   n+1, acc[mt][nt][1]);
            ep(m+8, n,   acc[mt][nt][2]);
            ep(m+8, n+1, acc[mt][nt][3]);
        }
    }
}

// ================= rest of pipeline =================
__global__ void __launch_bounds__(256) k_embed(const float* __restrict__ feat){
    int idx = blockIdx.x*256 + threadIdx.x;
    int b = idx >> 18, r = idx & 262143;
    int t = r >> 7, d = r & 127;
    int s = t >> 2, f = ((t & 3) << 7) + d;
    float inv = expf(-(2.0f*(float)f/512.0f)*9.210340371976184f);
    float ang = (float)s * inv;
    float pe = (f & 1) ? cosf(ang) : sinf(ang);
    float v = feat[(b*512 + s)*512 + f] + pe;
    g_x1[idx] = v; g_x2[idx] = v;
}

template<typename OutT>
__global__ void __launch_bounds__(128) k_layernorm(const float* __restrict__ in1,
                                                   const float* __restrict__ in2,
                                                   OutT* __restrict__ outp,
                                                   const float* __restrict__ gam,
                                                   const float* __restrict__ bet,
                                                   int pack){
    int row = blockIdx.x, d = threadIdx.x;
    float x = in1[row*128 + d];
    if (in2) x = 0.5f*(x + in2[row*128 + d]);
    __shared__ float sh[4];
    float s = x;
#pragma unroll
    for (int o=16;o>0;o>>=1) s += __shfl_xor_sync(0xffffffffu, s, o);
    if ((d & 31) == 0) sh[d>>5] = s;
    __syncthreads();
    float mean = (sh[0]+sh[1]+sh[2]+sh[3]) * (1.0f/128.0f);
    float c = x - mean;
    __syncthreads();
    float v = c*c;
#pragma unroll
    for (int o=16;o>0;o>>=1) v += __shfl_xor_sync(0xffffffffu, v, o);
    if ((d & 31) == 0) sh[d>>5] = v;
    __syncthreads();
    float var = (sh[0]+sh[1]+sh[2]+sh[3]) * (1.0f/128.0f);
    int orow = pack ? row + (row>>11)*128 : row;
    outp[orow*128 + d] = (OutT)(c * rsqrtf(var + 1e-5f) * gam[d] + bet[d]);
}

__global__ void __launch_bounds__(256) k_memfill(const float* __restrict__ mem){
    int idx = blockIdx.x*256 + threadIdx.x;
    int b = idx >> 12, r = idx & 4095;
    float4 v = ((const float4*)mem)[r];
    ((float4*)(g_aq + (b*2176 + 2048)*128))[r] = v;
}

// fp32 GEMM (qkv only — feeds LSH argmax, must stay fp32)
struct EQKV {
    float* out;
    __device__ __forceinline__ void operator()(int m, int n, float v) const {
        int b = m / 2176, t = m - b*2176;
        out[(((b<<3) + (n>>6))*2176 + t)*64 + (n & 63)] = v;
    }
};
template<class EP>
__global__ void __launch_bounds__(256) k_gemm(const float* __restrict__ A, int K,
                                              const float* __restrict__ Bm, int N,
                                              EP ep){
    __shared__ float As[2][16][132];
    __shared__ float Bs[2][16][132];
    int bm = blockIdx.y*128, bn = blockIdx.x*128;
    int tid = threadIdx.x, tx = tid & 15, ty = tid >> 4;
    int arow = tid >> 1, aq = tid & 1;
    int bkk = tid >> 4, bv = tid & 15;
    float acc[8][8] = {};
    const float* Arow = A + (bm+arow)*K;
    {
        float4 a0 = *(const float4*)(Arow + aq*4);
        float4 a1 = *(const float4*)(Arow + (aq+2)*4);
        float4 b0 = *(const float4*)(Bm + bkk*N + bn + bv*4);
        float4 b1 = *(const float4*)(Bm + bkk*N + bn + bv*4 + 64);
        As[0][aq*4+0][arow] = a0.x; As[0][aq*4+1][arow] = a0.y;
        As[0][aq*4+2][arow] = a0.z; As[0][aq*4+3][arow] = a0.w;
        As[0][aq*4+8][arow] = a1.x; As[0][aq*4+9][arow] = a1.y;
        As[0][aq*4+10][arow] = a1.z; As[0][aq*4+11][arow] = a1.w;
        *(float4*)&Bs[0][bkk][bv*4]      = b0;
        *(float4*)&Bs[0][bkk][bv*4 + 64] = b1;
    }
    __syncthreads();
    int nt = K >> 4;
    for (int t = 0; t < nt; t++){
        int cur = t & 1, nxt = cur ^ 1;
        float4 na0, na1, nb0, nb1;
        if (t+1 < nt){
            int k0 = (t+1) << 4;
            na0 = *(const float4*)(Arow + k0 + aq*4);
            na1 = *(const float4*)(Arow + k0 + (aq+2)*4);
            nb0 = *(const float4*)(Bm + (k0+bkk)*N + bn + bv*4);
            nb1 = *(const float4*)(Bm + (k0+bkk)*N + bn + bv*4 + 64);
        }
#pragma unroll
        for (int kk=0;kk<16;kk++){
            float4 a0 = *(float4*)&As[cur][kk][ty*8];
            float4 a1 = *(float4*)&As[cur][kk][ty*8+4];
            float4 b0 = *(float4*)&Bs[cur][kk][tx*8];
            float4 b1 = *(float4*)&Bs[cur][kk][tx*8+4];
            float av[8] = {a0.x,a0.y,a0.z,a0.w,a1.x,a1.y,a1.z,a1.w};
            float bv2[8] = {b0.x,b0.y,b0.z,b0.w,b1.x,b1.y,b1.z,b1.w};
#pragma unroll
            for (int i=0;i<8;i++)
#pragma unroll
                for (int j=0;j<8;j++) acc[i][j] = fmaf(av[i], bv2[j], acc[i][j]);
        }
        if (t+1 < nt){
            As[nxt][aq*4+0][arow] = na0.x; As[nxt][aq*4+1][arow] = na0.y;
            As[nxt][aq*4+2][arow] = na0.z; As[nxt][aq*4+3][arow] = na0.w;
            As[nxt][aq*4+8][arow] = na1.x; As[nxt][aq*4+9][arow] = na1.y;
            As[nxt][aq*4+10][arow] = na1.z; As[nxt][aq*4+11][arow] = na1.w;
            *(float4*)&Bs[nxt][bkk][bv*4]      = nb0;
            *(float4*)&Bs[nxt][bkk][bv*4 + 64] = nb1;
            __syncthreads();
        }
    }
#pragma unroll
    for (int i=0;i<8;i++)
#pragma unroll
        for (int j=0;j<8;j++) ep(bm + ty*8 + i, bn + tx*8 + j, acc[i][j]);
}

__global__ void __launch_bounds__(128) k_buckets(const float* __restrict__ rot){
    __shared__ float srot[4352];
    int tid = threadIdx.x;
    for (int i = tid; i < 4352; i += 128) srot[i] = rot[i];
    __syncthreads();
    int bh = blockIdx.x, t = blockIdx.y*128 + tid;
    int b = bh / 6, head = 2 + bh % 6;
    const float* qp = g_qk + (((b<<3) + head)*2176 + t)*64;
    float rv[68];
#pragma unroll
    for (int u=0;u<68;u++) rv[u] = 0.0f;
    for (int f=0; f<64; f++){
        float qf = qp[f];
        const float* rp = &srot[f*68];
#pragma unroll
        for (int u=0;u<68;u++) rv[u] = fmaf(qf, rp[u], rv[u]);
    }
#pragma unroll
    for (int h=0; h<4; h++){
        float best = rv[h*17]; int bi = 0;
#pragma unroll
        for (int i=1;i<17;i++){ float v = rv[h*17+i]; if (v > best){ best = v; bi = i; } }
#pragma unroll
        for (int i=0;i<17;i++){ float v = -rv[h*17+i]; if (v > best){ best = v; bi = 17+i; } }
        g_bkt[bh*8704 + h*2176 + t] = bi + h*34;
    }
}

__global__ void __launch_bounds__(64) k_sort(){
    __shared__ int hist[64][136];
    __shared__ int base[136];
    int bh = blockIdx.x, t = threadIdx.x;
    int* hrow = hist[t];
    for (int i=0;i<136;i++) hrow[i] = 0;
    const int* bk = g_bkt + bh*8704;
    int i0 = t*136;
    for (int i=0;i<136;i++) hrow[bk[i0+i]]++;
    __syncthreads();
    for (int c = t; c < 136; c += 64){
        int run = 0;
        for (int tt=0; tt<64; tt++){ int v = hist[tt][c]; hist[tt][c] = run; run += v; }
        base[c] = run;
    }
    __syncthreads();
    if (t == 0){
        int run = 0;
        for (int c=0;c<136;c++){ int v = base[c]; base[c] = run; run += v; }
    }
    __syncthreads();
    for (int i=0;i<136;i++){
        int idx = i0 + i, bb = bk[idx];
        int pos = base[bb] + hrow[bb]; hrow[bb]++;
        g_st  [bh*8704 + pos] = idx % 2176;
        g_undo[bh*8704 + idx] = pos;
    }
}

// ---- LSH chunk attention: HMMA dots + PV ----
__global__ void __launch_bounds__(256) k_lsh_attn(){
    extern __shared__ char smc[];
    __nv_bfloat16* skb = (__nv_bfloat16*)smc;              // [128][72] q/k rows
    __nv_bfloat16* svb = (__nv_bfloat16*)(smc + 18432);    // [128][72] v rows
    float* sd          = (float*)(smc + 36864);            // [64][128] logits
    __nv_bfloat16* sp  = (__nv_bfloat16*)(smc + 69632);    // [64][136] probs bf16
    float* scale       = (float*)(smc + 87040);            // [128]
    int*   skt         = (int*)(smc + 87552);              // [128]
    int bh = blockIdx.x, c = blockIdx.y, tid = threadIdx.x;
    int wid = tid >> 5, lane = tid & 31;
    int base  = bh*8704 + c*64;
    int pbase = bh*8704 + ((c + 135) % 136)*64;
    int b = bh / 6, head = 2 + bh % 6;
    int bhh = (b<<3) + head;
    for (int p = tid; p < 1024; p += 256){
        int row = p >> 3, c8 = p & 7;
        int src = (row < 64) ? g_st[base + row] : g_st[pbase + row - 64];
        const float4* qp = (const float4*)(g_qk + (bhh*2176 + src)*64 + c8*8);
        const float4* vp = (const float4*)(g_v  + (bhh*2176 + src)*64 + c8*8);
        *(uint4*)&skb[row*72 + c8*8] = f8_to_bf8(qp[0], qp[1]);
        *(uint4*)&svb[row*72 + c8*8] = f8_to_bf8(vp[0], vp[1]);
    }
    if (tid < 128)
        skt[tid] = (tid < 64) ? g_st[base + tid] : g_st[pbase + tid - 64];
    __syncthreads();
    if (tid < 128){
        float s = 0.f;
        const uint32_t* rp = (const uint32_t*)(skb + tid*72);
#pragma unroll
        for (int i = 0; i < 32; i++){
            float2 f = __bfloat1622float2(*(const __nv_bfloat162*)&rp[i]);
            s += f.x*f.x + f.y*f.y;
        }
        scale[tid] = 1.0f / fmaxf(sqrtf(s), 1e-12f);
    }
    __syncthreads();
    int wm = wid >> 1, wn = wid & 1;
    {
        float dacc[8][4] = {};
#pragma unroll
        for (int s = 0; s < 4; s++){
            uint32_t af[4];
            ldm4(af[0],af[1],af[2],af[3],
                 smem_u32(&skb[(wm*16 + (lane & 15))*72 + s*16 + (lane >> 4)*8]));
            uint32_t bf[8][2];
#pragma unroll
            for (int nt16 = 0; nt16 < 4; nt16++){
                int mi = lane >> 3;
                uint32_t r0,r1,r2,r3;
                ldm4(r0,r1,r2,r3,
                     smem_u32(&skb[(wn*64 + nt16*16 + (mi >> 1)*8 + (lane & 7))*72 + s*16 + (mi & 1)*8]));
                bf[nt16*2][0]   = r0; bf[nt16*2][1]   = r1;
                bf[nt16*2+1][0] = r2; bf[nt16*2+1][1] = r3;
            }
#pragma unroll
            for (int nt = 0; nt < 8; nt++)
                mma16816(dacc[nt], af, bf[nt]);
        }
#pragma unroll
        for (int nt = 0; nt < 8; nt++){
            int row = wm*16 + (lane >> 2);
            int col = wn*64 + nt*8 + (lane & 3)*2;
#pragma unroll
            for (int e = 0; e < 4; e++){
                int r = row + (e >> 1)*8, cc = col + (e & 1);
                int tq = skt[r], tk = skt[cc];
                float v = dacc[nt][e]*scale[cc]*0.125f;
                if (tq < tk)       v = -1e9f;
                else if (tq == tk) v = -5e4f;
                sd[r*128 + cc] = v;
            }
        }
    }
    __syncthreads();
    {
        int warp = wid, ln = lane;
        for (int rr=0; rr<8; rr++){
            int row = warp*8 + rr;
            float d0[4];
#pragma unroll
            for (int j=0;j<4;j++) d0[j] = sd[row*128 + ln + 32*j];
            float m = fmaxf(fmaxf(d0[0],d0[1]), fmaxf(d0[2],d0[3]));
#pragma unroll
            for (int o=16;o>0;o>>=1) m = fmaxf(m, __shfl_xor_sync(0xffffffffu, m, o));
            float p[4], s = 0.f;
#pragma unroll
            for (int j=0;j<4;j++){ p[j] = __expf(d0[j]-m); s += p[j]; }
#pragma unroll
            for (int o=16;o>0;o>>=1) s += __shfl_xor_sync(0xffffffffu, s, o);
            float inv = 1.0f/s;
#pragma unroll
            for (int j=0;j<4;j++) sp[row*136 + ln + 32*j] = __float2bfloat16(p[j]*inv);
            if (ln == 0) g_slog[base + row] = m + __logf(s);
        }
    }
    __syncthreads();
    {
        float pacc[4][4] = {};
#pragma unroll
        for (int s = 0; s < 8; s++){
            uint32_t af[4];
            ldm4(af[0],af[1],af[2],af[3],
                 smem_u32(&sp[(wm*16 + (lane & 15))*136 + s*16 + (lane >> 4)*8]));
            uint32_t bf[4][2];
#pragma unroll
            for (int nt16 = 0; nt16 < 2; nt16++){
                int mi = lane >> 3;
                uint32_t r0,r1,r2,r3;
                ldm4t(r0,r1,r2,r3,
                      smem_u32(&svb[(s*16 + (mi & 1)*8 + (lane & 7))*72 + wn*32 + nt16*16 + (mi >> 1)*8]));
                bf[nt16*2][0]   = r0; bf[nt16*2][1]   = r1;
                bf[nt16*2+1][0] = r2; bf[nt16*2+1][1] = r3;
            }
#pragma unroll
            for (int nt = 0; nt < 4; nt++)
                mma16816(pacc[nt], af, bf[nt]);
        }
#pragma unroll
        for (int nt = 0; nt < 4; nt++){
            int row = wm*16 + (lane >> 2);
            int col = wn*32 + nt*8 + (lane & 3)*2;
            g_so[(base + row)*64 + col]     = pacc[nt][0];
            g_so[(base + row)*64 + col + 1] = pacc[nt][1];
            g_so[(base + row + 8)*64 + col]     = pacc[nt][2];
            g_so[(base + row + 8)*64 + col + 1] = pacc[nt][3];
        }
    }
}

__global__ void __launch_bounds__(256) k_unsort(){
    int bh = blockIdx.y, tid = threadIdx.x;
    int g = tid >> 6, d = tid & 63;
    int t = blockIdx.x*4 + g;
    __shared__ int pos[4][4]; __shared__ float w[4][4];
    if (d < 4){
        int p = g_undo[bh*8704 + d*2176 + t];
        pos[g][d] = p; w[g][d] = g_slog[bh*8704 + p];
    }
    __syncthreads();
    if (d == 0){
        float m = fmaxf(fmaxf(w[g][0],w[g][1]), fmaxf(w[g][2],w[g][3]));
        float s = 0.f;
        for (int h=0;h<4;h++){ w[g][h] = __expf(w[g][h]-m); s += w[g][h]; }
        float inv = 1.0f/s;
        for (int h=0;h<4;h++) w[g][h] *= inv;
    }
    __syncthreads();
    float o = 0.f;
    for (int h=0;h<4;h++) o += w[g][h]*g_so[(bh*8704 + pos[g][h])*64 + d];
    int b = bh / 6, head = 2 + bh % 6;
    g_am[(b*2048 + t)*512 + head*64 + d] = __float2bfloat16(o);
}

// ---- local windowed attention: HMMA dots + PV, 64 q x 256 kv ----
__global__ void __launch_bounds__(256) k_local_attn(){
    extern __shared__ char smc[];
    __nv_bfloat16* skv = (__nv_bfloat16*)smc;              // [256][72] k rows (0-127 prev, 128-255 own)
    __nv_bfloat16* svb = (__nv_bfloat16*)(smc + 36864);    // [256][72] v rows
    float* sd          = (float*)(smc + 73728);            // [64][256] logits fp32
    __nv_bfloat16* sp  = (__nv_bfloat16*)(smc + 139264);   // [64][264] probs bf16
    float* scale       = (float*)(smc + 173056);           // [256]
    int bh = blockIdx.x, b = bh >> 1, head = bh & 1;
    int win = blockIdx.y, half = blockIdx.z;
    int tid = threadIdx.x, wid = tid >> 5, lane = tid & 31;
    const float* qbase = g_qk + (((b<<3) + head)*2176)*64;
    const float* vbase = g_v  + (((b<<3) + head)*2176)*64;
    int q0 = win*128 + half*64;
    int qrow = 128 + half*64;
    for (int p = tid; p < 2048; p += 256){
        int row = p >> 3, c8 = p & 7;
        uint4 kv, vv;
        if (row < 128 && win == 0){
            kv = make_uint4(0,0,0,0); vv = kv;
        } else {
            int t = (row < 128) ? (win-1)*128 + row : win*128 + row - 128;
            const float4* qp = (const float4*)(qbase + t*64 + c8*8);
            const float4* vp = (const float4*)(vbase + t*64 + c8*8);
            kv = f8_to_bf8(qp[0], qp[1]);
            vv = f8_to_bf8(vp[0], vp[1]);
        }
        *(uint4*)&skv[row*72 + c8*8] = kv;
        *(uint4*)&svb[row*72 + c8*8] = vv;
    }
    __syncthreads();
    {
        float s = 0.f;
        const uint32_t* rp = (const uint32_t*)(skv + tid*72);
#pragma unroll
        for (int i = 0; i < 32; i++){
            float2 f = __bfloat1622float2(*(const __nv_bfloat162*)&rp[i]);
            s += f.x*f.x + f.y*f.y;
        }
        scale[tid] = 1.0f / fmaxf(sqrtf(s), 1e-12f);
    }
    __syncthreads();
    int wm = wid & 3, wn = wid >> 2;    // dots: 4 m-tiles x 2 n-tiles (16 x 128 per warp)
    {
        float dacc[16][4] = {};
#pragma unroll
        for (int s = 0; s < 4; s++){
            uint32_t af[4];
            ldm4(af[0],af[1],af[2],af[3],
                 smem_u32(&skv[(qrow + wm*16 + (lane & 15))*72 + s*16 + (lane >> 4)*8]));
            uint32_t bf[16][2];
#pragma unroll
            for (int nt16 = 0; nt16 < 8; nt16++){
                int mi = lane >> 3;
                uint32_t r0,r1,r2,r3;
                ldm4(r0,r1,r2,r3,
                     smem_u32(&skv[(wn*128 + nt16*16 + (mi >> 1)*8 + (lane & 7))*72 + s*16 + (mi & 1)*8]));
                bf[nt16*2][0]   = r0; bf[nt16*2][1]   = r1;
                bf[nt16*2+1][0] = r2; bf[nt16*2+1][1] = r3;
            }
#pragma unroll
            for (int nt = 0; nt < 16; nt++)
                mma16816(dacc[nt], af, bf[nt]);
        }
#pragma unroll
        for (int nt = 0; nt < 16; nt++){
            int row = wm*16 + (lane >> 2);
            int col = wn*128 + nt*8 + (lane & 3)*2;
#pragma unroll
            for (int e = 0; e < 4; e++){
                int r = row + (e >> 1)*8, jc = col + (e & 1);
                int tq = q0 + r;
                float v = dacc[nt][e]*scale[jc]*0.125f;
                if (jc < 128){
                    if (win == 0) v = -1e9f;
                    else {
                        int tk = (win-1)*128 + jc;
                        if (tq == tk) v = -5e4f; else if (tq < tk) v = -1e9f;
                    }
                } else {
                    int tk = win*128 + jc - 128;
                    if (tq == tk) v = -5e4f; else if (tq < tk) v = -1e9f;
                }
                sd[r*256 + jc] = v;
            }
        }
    }
    __syncthreads();
    {   // softmax over 256 cols; probs bf16
        int warp = wid, ln = lane;
        for (int rr=0; rr<8; rr++){
            int row = warp*8 + rr;
            float d0[8];
#pragma unroll
            for (int j=0;j<8;j++) d0[j] = sd[row*256 + ln + 32*j];
            float m = d0[0];
#pragma unroll
            for (int j=1;j<8;j++) m = fmaxf(m, d0[j]);
#pragma unroll
            for (int o=16;o>0;o>>=1) m = fmaxf(m, __shfl_xor_sync(0xffffffffu, m, o));
            float p[8], s = 0.f;
#pragma unroll
            for (int j=0;j<8;j++){ p[j] = __expf(d0[j]-m); s += p[j]; }
#pragma unroll
            for (int o=16;o>0;o>>=1) s += __shfl_xor_sync(0xffffffffu, s, o);
            float inv = 1.0f/s;
#pragma unroll
            for (int j=0;j<8;j++) sp[row*264 + ln + 32*j] = __float2bfloat16(p[j]*inv);
        }
    }
    __syncthreads();
    {   // PV: C[64][64] = P[64][256] @ V[256][64]; warp tile (wm2,wn2) = 4m x 2n, 16x32
        int wm2 = wid & 3, wn2 = wid >> 2;
        float pacc[4][4] = {};
#pragma unroll
        for (int s = 0; s < 16; s++){
            uint32_t af[4];
            ldm4(af[0],af[1],af[2],af[3],
                 smem_u32(&sp[(wm2*16 + (lane & 15))*264 + s*16 + (lane >> 4)*8]));
            uint32_t bf[4][2];
#pragma unroll
            for (int nt16 = 0; nt16 < 2; nt16++){
                int mi = lane >> 3;
                uint32_t r0,r1,r2,r3;
                ldm4t(r0,r1,r2,r3,
                      smem_u32(&svb[(s*16 + (mi & 1)*8 + (lane & 7))*72 + wn2*32 + nt16*16 + (mi >> 1)*8]));
                bf[nt16*2][0]   = r0; bf[nt16*2][1]   = r1;
                bf[nt16*2+1][0] = r2; bf[nt16*2+1][1] = r3;
            }
#pragma unroll
            for (int nt = 0; nt < 4; nt++)
                mma16816(pacc[nt], af, bf[nt]);
        }
#pragma unroll
        for (int nt = 0; nt < 4; nt++){
            int row = wm2*16 + (lane >> 2);
            int col = wn2*32 + nt*8 + (lane & 3)*2;
#pragma unroll
            for (int e = 0; e < 4; e++){
                int r = row + (e >> 1)*8, cc = col + (e & 1);
                int t = q0 + r;
                if (t < 2048)
                    g_am[(b*2048 + t)*512 + head*64 + cc] = __float2bfloat16(pacc[nt][e]);
            }
        }
    }
}

__global__ void __launch_bounds__(128) k_pool(const float* __restrict__ in, float* __restrict__ out){
    int b = blockIdx.x >> 2, sub = blockIdx.x & 3, d = threadIdx.x;
    const float* p = in + (b*2048 + sub)*128 + d;
    float s = 0.f;
    for (int i=0;i<512;i++) s += p[i*512];
    out[b*512 + sub*128 + d] = s * (1.0f/512.0f);
}

extern "C" void kernel_launch(void* const* d_in, const int* in_sizes, int n_in,
                              void* d_out, int out_size){
    const float* features  = (const float*)d_in[0];
    const float* w_qk      = (const float*)d_in[1];
    const float* w_v       = (const float*)d_in[2];
    const float* mem_kv    = (const float*)d_in[3];
    const float* w_out     = (const float*)d_in[4];
    const float* b_out     = (const float*)d_in[5];
    const float* ln1_g     = (const float*)d_in[6];
    const float* ln1_b     = (const float*)d_in[7];
    const float* ff_w1     = (const float*)d_in[8];
    const float* ff_b1     = (const float*)d_in[9];
    const float* ff_w2     = (const float*)d_in[10];
    const float* ff_b2     = (const float*)d_in[11];
    const float* ln2_g     = (const float*)d_in[12];
    const float* ln2_b     = (const float*)d_in[13];
    const float* lnf_g     = (const float*)d_in[14];
    const float* lnf_b     = (const float*)d_in[15];
    const float* rotations = (const float*)d_in[16];
    float* out = (float*)d_out;

    float *x1,*x2,*fin,*aq,*qk,*vv;
    __nv_bfloat16 *ain,*am,*ff,*wt_out,*wt_ff1,*wt_ff2;
    cudaGetSymbolAddress((void**)&x1,  g_x1);
    cudaGetSymbolAddress((void**)&x2,  g_x2);
    cudaGetSymbolAddress((void**)&fin, g_fin);
    cudaGetSymbolAddress((void**)&aq,  g_aq);
    cudaGetSymbolAddress((void**)&qk,  g_qk);
    cudaGetSymbolAddress((void**)&vv,  g_v);
    cudaGetSymbolAddress((void**)&ain, g_ain);
    cudaGetSymbolAddress((void**)&am,  g_am);
    cudaGetSymbolAddress((void**)&ff,  g_ff);
    cudaGetSymbolAddress((void**)&wt_out, g_wt_out);
    cudaGetSymbolAddress((void**)&wt_ff1, g_wt_ff1);
    cudaGetSymbolAddress((void**)&wt_ff2, g_wt_ff2);

    const int LSH_SMEM = 88064;
    const int LOC_SMEM = 174080;
    cudaFuncSetAttribute(k_lsh_attn,   cudaFuncAttributeMaxDynamicSharedMemorySize, LSH_SMEM);
    cudaFuncSetAttribute(k_local_attn, cudaFuncAttributeMaxDynamicSharedMemorySize, LOC_SMEM);

    for (int i = 0; i < 2; i++){
        k_wcvt<<<(128*512)/256,256>>>(w_out + i*512*128, wt_out + i*128*512, 512, 128);
        k_wcvt<<<(512*128)/256,256>>>(ff_w1 + i*128*512, wt_ff1 + i*512*128, 128, 512);
        k_wcvt<<<(128*512)/256,256>>>(ff_w2 + i*512*128, wt_ff2 + i*128*512, 512, 128);
    }

    k_embed<<<8192, 256>>>(features);

    for (int i = 0; i < 2; i++){
        k_layernorm<float><<<16384,128>>>(x2, (const float*)0, aq, ln1_g + i*128, ln1_b + i*128, 1);
        k_memfill<<<128,256>>>(mem_kv + i*128*128);
        EQKV eq; eq.out = qk;
        EQKV ev; ev.out = vv;
        k_gemm<<<dim3(4,136),256>>>(aq, 128, w_qk + i*128*512, 512, eq);
        k_gemm<<<dim3(4,136),256>>>(aq, 128, w_v  + i*128*512, 512, ev);
        k_local_attn<<<dim3(16,17,2),256,LOC_SMEM>>>();
        k_buckets<<<dim3(48,17),128>>>(rotations + i*64*4*17);
        k_sort<<<48,64>>>();
        k_lsh_attn<<<dim3(48,136),256,LSH_SMEM>>>();
        k_unsort<<<dim3(512,48),256>>>();
        EAddBias e1; e1.out = x1; e1.bias = b_out + i*128; e1.ld = 128;
        k_tgemm<<<dim3(1,128),256>>>(am, 512, wt_out + i*128*512, e1);
        k_layernorm<__nv_bfloat16><<<16384,128>>>(x1, (const float*)0, ain, ln2_g + i*128, ln2_b + i*128, 0);
        EGelu eg; eg.out = ff; eg.bias = ff_b1 + i*512;
        k_tgemm<<<dim3(4,128),256>>>(ain, 128, wt_ff1 + i*512*128, eg);
        EAddBias e2; e2.out = x2; e2.bias = ff_b2 + i*128; e2.ld = 128;
        k_tgemm<<<dim3(1,128),256>>>(ff, 512, wt_ff2 + i*128*512, e2);
    }
    k_layernorm<float><<<16384,128>>>(x1, x2, fin, lnf_g, lnf_b, 0);
    k_pool<<<32,128>>>(fin, out);
}